// round 1
// baseline (speedup 1.0000x reference)
#include <cuda_runtime.h>
#include <float.h>
#include <math.h>

// ---------------- problem constants ----------------
#define B_    4
#define T_    32768
#define BT    (B_ * T_)          // 131072 points
#define RESO_ 128
#define R2_   (RESO_ * RESO_)    // 16384
#define NSEG  (B_ * R2_)         // 65536 segments
#define H     128
#define H2    256
#define CDIM  64
#define NB    5

// ---------------- scratch (device globals, no allocation) ----------------
__device__ int   g_idx[3][BT];            // flat segment index per plane
__device__ float g_x[(size_t)BT * H2];    // resblock input (concat) / fc_pos out
__device__ float g_hidden[(size_t)BT * H];
__device__ float g_net[(size_t)BT * H];
__device__ float g_segmax[3][(size_t)NSEG * H];
__device__ float g_c[(size_t)BT * CDIM];
__device__ float g_sums[3][(size_t)NSEG * CDIM];
__device__ int   g_cnt[3][NSEG];

// ---------------- helpers ----------------
__device__ __forceinline__ int norm_bin(float v) {
    float u = v / 1.10001f + 0.5f;               // (1 + PADDING + 1e-5)
    u = fminf(fmaxf(u, 0.0f), 0.99999f);          // clip [0, 1-1e-5]
    int q = (int)(u * 128.0f);
    return q < 127 ? q : 127;
}

// float atomic max via signbit-split int/uint atomics (exact, handles -0.0)
__device__ __forceinline__ void atomicMaxF(float* addr, float v) {
    if (!signbit(v)) {
        atomicMax((int*)addr, __float_as_int(v));
    } else {
        atomicMin((unsigned int*)addr, __float_as_uint(v));
    }
}

// ---------------- kernels ----------------
__global__ void k_idx(const float* __restrict__ p) {
    int i = blockIdx.x * 256 + threadIdx.x;
    if (i >= BT) return;
    float x = p[3 * i + 0], y = p[3 * i + 1], z = p[3 * i + 2];
    int base = (i / T_) * R2_;
    int ix = norm_bin(x), iy = norm_bin(y), iz = norm_bin(z);
    g_idx[0][i] = base + ix + RESO_ * iz;  // xz
    g_idx[1][i] = base + ix + RESO_ * iy;  // xy
    g_idx[2][i] = base + iy + RESO_ * iz;  // yz
}

__global__ void k_fcpos(const float* __restrict__ p,
                        const float* __restrict__ w,
                        const float* __restrict__ b) {
    int i = blockIdx.x;          // point
    int j = threadIdx.x;         // output channel (256)
    float x0 = p[3 * i], x1 = p[3 * i + 1], x2 = p[3 * i + 2];
    g_x[(size_t)i * H2 + j] = x0 * w[j] + x1 * w[H2 + j] + x2 * w[2 * H2 + j] + b[j];
}

// C[M,N] (=|+=) (relu?)(A[M,K]) @ B[K,N] (+ bias)
// BM=128, BN=64, BK=16, thread tile 8x4, 256 threads. M%128==0, N%64==0, K%16==0.
template <bool RELU_A, bool ACCUM, bool BIAS>
__global__ void __launch_bounds__(256)
k_gemm(const float* __restrict__ A, const float* __restrict__ Bw,
       const float* __restrict__ bias, float* __restrict__ C,
       int M, int N, int K) {
    __shared__ float As[16][128];
    __shared__ float Bs[16][64];
    int tid = threadIdx.x;
    int bm = blockIdx.x * 128;
    int bn = blockIdx.y * 64;
    int ty = tid >> 4;          // 0..15
    int tx = tid & 15;          // 0..15

    float acc[8][4];
#pragma unroll
    for (int m = 0; m < 8; m++)
#pragma unroll
        for (int n = 0; n < 4; n++) acc[m][n] = 0.0f;

    int arow0 = tid >> 2;            // 0..63
    int acol  = (tid & 3) * 4;       // 0,4,8,12
    int brow  = tid >> 4;            // 0..15
    int bcol  = (tid & 15) * 4;      // 0..60

    for (int kt = 0; kt < K; kt += 16) {
#pragma unroll
        for (int hh = 0; hh < 2; hh++) {
            int row = arow0 + hh * 64;
            float4 a4 = *reinterpret_cast<const float4*>(
                &A[(size_t)(bm + row) * K + kt + acol]);
            if (RELU_A) {
                a4.x = fmaxf(a4.x, 0.0f); a4.y = fmaxf(a4.y, 0.0f);
                a4.z = fmaxf(a4.z, 0.0f); a4.w = fmaxf(a4.w, 0.0f);
            }
            As[acol + 0][row] = a4.x;
            As[acol + 1][row] = a4.y;
            As[acol + 2][row] = a4.z;
            As[acol + 3][row] = a4.w;
        }
        *reinterpret_cast<float4*>(&Bs[brow][bcol]) =
            *reinterpret_cast<const float4*>(&Bw[(size_t)(kt + brow) * N + bn + bcol]);
        __syncthreads();

#pragma unroll
        for (int k = 0; k < 16; k++) {
            float a[8], b[4];
#pragma unroll
            for (int m = 0; m < 8; m++) a[m] = As[k][ty * 8 + m];
#pragma unroll
            for (int n = 0; n < 4; n++) b[n] = Bs[k][tx * 4 + n];
#pragma unroll
            for (int m = 0; m < 8; m++)
#pragma unroll
                for (int n = 0; n < 4; n++) acc[m][n] += a[m] * b[n];
        }
        __syncthreads();
    }

    float bv[4] = {0.f, 0.f, 0.f, 0.f};
    if (BIAS) {
#pragma unroll
        for (int n = 0; n < 4; n++) bv[n] = bias[bn + tx * 4 + n];
    }
#pragma unroll
    for (int m = 0; m < 8; m++) {
        size_t o = (size_t)(bm + ty * 8 + m) * N + bn + tx * 4;
        float4 v;
        v.x = acc[m][0] + bv[0];
        v.y = acc[m][1] + bv[1];
        v.z = acc[m][2] + bv[2];
        v.w = acc[m][3] + bv[3];
        if (ACCUM) {
            float4 c = *reinterpret_cast<float4*>(&C[o]);
            v.x += c.x; v.y += c.y; v.z += c.z; v.w += c.w;
        }
        *reinterpret_cast<float4*>(&C[o]) = v;
    }
}

__global__ void k_seginit() {
    size_t t = (size_t)blockIdx.x * 256 + threadIdx.x;   // 3*NSEG*H
    (&g_segmax[0][0])[t] = -FLT_MAX;
}

__global__ void k_scatmax() {
    int t = blockIdx.x * 256 + threadIdx.x;   // BT*H
    int i = t >> 7, f = t & 127;
    float v = g_net[t];
#pragma unroll
    for (int pl = 0; pl < 3; pl++)
        atomicMaxF(&g_segmax[pl][(size_t)g_idx[pl][i] * H + f], v);
}

__global__ void k_concat() {
    int t = blockIdx.x * 256 + threadIdx.x;   // BT*H
    int i = t >> 7, f = t & 127;
    float s = 0.0f;
#pragma unroll
    for (int pl = 0; pl < 3; pl++)
        s += g_segmax[pl][(size_t)g_idx[pl][i] * H + f];
    g_x[(size_t)i * H2 + f] = g_net[t];
    g_x[(size_t)i * H2 + H + f] = s;
}

__global__ void k_zerosum() {
    size_t t = (size_t)blockIdx.x * 256 + threadIdx.x;   // 3*NSEG*CDIM
    (&g_sums[0][0])[t] = 0.0f;
}

__global__ void k_zerocnt() {
    int t = blockIdx.x * 256 + threadIdx.x;              // 3*NSEG
    (&g_cnt[0][0])[t] = 0;
}

__global__ void k_scatsum() {
    int t = blockIdx.x * 256 + threadIdx.x;   // BT*CDIM
    int i = t >> 6, ch = t & 63;
    float v = g_c[t];
#pragma unroll
    for (int pl = 0; pl < 3; pl++)
        atomicAdd(&g_sums[pl][(size_t)g_idx[pl][i] * CDIM + ch], v);
}

__global__ void k_scatcnt() {
    int i = blockIdx.x * 256 + threadIdx.x;   // BT
#pragma unroll
    for (int pl = 0; pl < 3; pl++)
        atomicAdd(&g_cnt[pl][g_idx[pl][i]], 1);
}

// out layout: [plane][b][ch][pix], pix = ix + 128*iy (== segment index within batch)
__global__ void k_out(float* __restrict__ out) {
    int t = blockIdx.x * 256 + threadIdx.x;   // 3*B*CDIM*R2 = 12582912
    int pix = t & (R2_ - 1);
    int ch  = (t >> 14) & 63;
    int b   = (t >> 20) & 3;
    int pl  = t >> 22;
    int seg = b * R2_ + pix;
    float cnt = (float)max(g_cnt[pl][seg], 1);
    out[t] = g_sums[pl][(size_t)seg * CDIM + ch] / cnt;
}

// ---------------- launcher ----------------
extern "C" void kernel_launch(void* const* d_in, const int* in_sizes, int n_in,
                              void* d_out, int out_size) {
    const float* p   = (const float*)d_in[0];
    const float* fw  = (const float*)d_in[1];
    const float* fb  = (const float*)d_in[2];
    const float* w0  = (const float*)d_in[3];   // [5,256,128]
    const float* b0  = (const float*)d_in[4];   // [5,128]
    const float* w1  = (const float*)d_in[5];   // [5,128,128]
    const float* b1  = (const float*)d_in[6];   // [5,128]
    const float* ws  = (const float*)d_in[7];   // [5,256,128]
    const float* fcw = (const float*)d_in[8];   // [128,64]
    const float* fcb = (const float*)d_in[9];   // [64]
    float* out = (float*)d_out;

    float *gx, *gh, *gn, *gc;
    cudaGetSymbolAddress((void**)&gx, g_x);
    cudaGetSymbolAddress((void**)&gh, g_hidden);
    cudaGetSymbolAddress((void**)&gn, g_net);
    cudaGetSymbolAddress((void**)&gc, g_c);

    k_idx<<<BT / 256, 256>>>(p);
    k_fcpos<<<BT, 256>>>(p, fw, fb);

    dim3 grid128(BT / 128, H / 64);     // N=128
    for (int i = 0; i < NB; i++) {
        if (i > 0) {
            k_seginit<<<(3 * NSEG * H) / 256, 256>>>();
            k_scatmax<<<(BT * H) / 256, 256>>>();
            k_concat<<<(BT * H) / 256, 256>>>();
        }
        // hidden = relu(x) @ w0 + b0
        k_gemm<true, false, true><<<grid128, 256>>>(
            gx, w0 + (size_t)i * H2 * H, b0 + (size_t)i * H, gh, BT, H, H2);
        // net = relu(hidden) @ w1 + b1
        k_gemm<true, false, true><<<grid128, 256>>>(
            gh, w1 + (size_t)i * H * H, b1 + (size_t)i * H, gn, BT, H, H);
        // net += x @ ws
        k_gemm<false, true, false><<<grid128, 256>>>(
            gx, ws + (size_t)i * H2 * H, nullptr, gn, BT, H, H2);
    }

    // c = net @ fc_c_w + fc_c_b
    k_gemm<false, false, true><<<dim3(BT / 128, CDIM / 64), 256>>>(
        gn, fcw, fcb, gc, BT, CDIM, H);

    k_zerosum<<<(3 * NSEG * CDIM) / 256, 256>>>();
    k_zerocnt<<<(3 * NSEG) / 256, 256>>>();
    k_scatsum<<<(BT * CDIM) / 256, 256>>>();
    k_scatcnt<<<BT / 256, 256>>>();
    k_out<<<(3 * B_ * CDIM * R2_) / 256, 256>>>(out);
}

// round 2
// speedup vs baseline: 1.5525x; 1.5525x over previous
#include <cuda_runtime.h>
#include <float.h>
#include <math.h>

// ---------------- problem constants ----------------
#define B_    4
#define T_    32768
#define BT    (B_ * T_)          // 131072 points
#define RESO_ 128
#define R2_   (RESO_ * RESO_)    // 16384
#define NSEG  (B_ * R2_)         // 65536 segments
#define H     128
#define H2    256
#define CDIM  64
#define NB    5

// ---------------- scratch (device globals, no allocation) ----------------
__device__ int   g_idx[3][BT];            // flat segment index per plane
__device__ int   g_rank[3][BT];           // rank of point within its bin
__device__ int   g_bcnt[3][NSEG];         // points per bin
__device__ int   g_boff[3][NSEG];         // exclusive prefix offsets
__device__ int   g_pts[3][BT];            // CSR point lists
__device__ float g_x[(size_t)BT * H2];    // resblock input (concat) / fc_pos out
__device__ float g_hidden[(size_t)BT * H];
__device__ float g_net[(size_t)BT * H];
__device__ float g_segmax[3][(size_t)NSEG * H];
__device__ float g_c[(size_t)BT * CDIM];
__device__ float g_mean[3][(size_t)NSEG * CDIM];

// ---------------- helpers ----------------
__device__ __forceinline__ int norm_bin(float v) {
    float u = v / 1.10001f + 0.5f;                // (1 + PADDING + 1e-5)
    u = fminf(fmaxf(u, 0.0f), 0.99999f);          // clip [0, 1-1e-5]
    int q = (int)(u * 128.0f);
    return q < 127 ? q : 127;
}

__device__ __forceinline__ unsigned f2tf32(float f) {
    unsigned u;
    asm("cvt.rna.tf32.f32 %0, %1;" : "=r"(u) : "f"(f));
    return u;
}

// ---------------- index / CSR build ----------------
__global__ void k_idx(const float* __restrict__ p) {
    int i = blockIdx.x * 256 + threadIdx.x;
    if (i >= BT) return;
    float x = p[3 * i + 0], y = p[3 * i + 1], z = p[3 * i + 2];
    int base = (i / T_) * R2_;
    int ix = norm_bin(x), iy = norm_bin(y), iz = norm_bin(z);
    g_idx[0][i] = base + ix + RESO_ * iz;  // xz
    g_idx[1][i] = base + ix + RESO_ * iy;  // xy
    g_idx[2][i] = base + iy + RESO_ * iz;  // yz
}

__global__ void k_zerobcnt() {
    int t = blockIdx.x * 256 + threadIdx.x;   // 3*NSEG
    (&g_bcnt[0][0])[t] = 0;
}

__global__ void k_count() {
    int i = blockIdx.x * 256 + threadIdx.x;   // BT
#pragma unroll
    for (int pl = 0; pl < 3; pl++) {
        int bin = g_idx[pl][i];
        g_rank[pl][i] = atomicAdd(&g_bcnt[pl][bin], 1);
    }
}

__global__ void k_scan() {        // one block per plane, 1024 threads
    int pl = blockIdx.x;
    int tid = threadIdx.x;
    __shared__ int sh[1024];
    __shared__ int carry_sh;
    if (tid == 0) carry_sh = 0;
    __syncthreads();
    for (int base = 0; base < NSEG; base += 1024) {
        int v = g_bcnt[pl][base + tid];
        sh[tid] = v;
        __syncthreads();
        for (int off = 1; off < 1024; off <<= 1) {
            int t = (tid >= off) ? sh[tid - off] : 0;
            __syncthreads();
            sh[tid] += t;
            __syncthreads();
        }
        int incl = sh[tid];
        g_boff[pl][base + tid] = carry_sh + incl - v;   // exclusive
        __syncthreads();
        if (tid == 1023) carry_sh += incl;
        __syncthreads();
    }
}

__global__ void k_scatter() {
    int i = blockIdx.x * 256 + threadIdx.x;   // BT
#pragma unroll
    for (int pl = 0; pl < 3; pl++) {
        int bin = g_idx[pl][i];
        g_pts[pl][g_boff[pl][bin] + g_rank[pl][i]] = i;
    }
}

// ---------------- fc_pos (exact fp32, tiny) ----------------
__global__ void k_fcpos(const float* __restrict__ p,
                        const float* __restrict__ w,
                        const float* __restrict__ b) {
    int i = blockIdx.x;          // point
    int j = threadIdx.x;         // output channel (256)
    float x0 = p[3 * i], x1 = p[3 * i + 1], x2 = p[3 * i + 2];
    g_x[(size_t)i * H2 + j] = x0 * w[j] + x1 * w[H2 + j] + x2 * w[2 * H2 + j] + b[j];
}

// ---------------- TF32 tensor-core GEMM ----------------
// C[M,BN] (=|+=) (relu?)(A[M,K]) @ W[K,BN] (+ bias).  BM=128, BK=16, 256 thr.
template <int BN, bool RELU_A, bool ACCUM, bool BIAS, int WARPS_M, int WARPS_N>
__global__ void __launch_bounds__(256)
k_mma(const float* __restrict__ A, const float* __restrict__ W,
      const float* __restrict__ bias, float* __restrict__ C,
      int M, int K) {
    constexpr int BM = 128, BK = 16;
    constexpr int WM = BM / WARPS_M, WN = BN / WARPS_N;
    constexpr int TM = WM / 16, TN = WN / 8;
    constexpr int ASr = BM + 8, BSr = BN + 8;    // stride mod 32 = 8 -> conflict-free
    __shared__ unsigned As[2][BK][ASr];
    __shared__ unsigned Bs[2][BK][BSr];

    int tid = threadIdx.x;
    int bm = blockIdx.x * BM;
    int w = tid >> 5, lane = tid & 31;
    int wm = w % WARPS_M, wn = w / WARPS_M;
    int lr = lane >> 2, lc = lane & 3;

    float acc[TM][TN][4];
#pragma unroll
    for (int mi = 0; mi < TM; mi++)
#pragma unroll
        for (int ni = 0; ni < TN; ni++)
#pragma unroll
            for (int q = 0; q < 4; q++) acc[mi][ni][q] = 0.0f;

    int arow = tid >> 2;             // 0..63
    int acol = (tid & 3) * 4;        // 0,4,8,12
    int brow = tid >> 4;             // 0..15
    int bcol = (tid & 15) * 4;       // 0..60

    float4 ar[2];
    float4 br[BN / 64];

    // prologue: load tile 0 into smem buf 0
    {
#pragma unroll
        for (int hh = 0; hh < 2; hh++)
            ar[hh] = *(const float4*)&A[(size_t)(bm + arow + hh * 64) * K + acol];
#pragma unroll
        for (int nv = 0; nv < BN / 64; nv++)
            br[nv] = *(const float4*)&W[(size_t)brow * BN + bcol + nv * 64];
#pragma unroll
        for (int hh = 0; hh < 2; hh++) {
            float4 a4 = ar[hh];
            if (RELU_A) {
                a4.x = fmaxf(a4.x, 0.f); a4.y = fmaxf(a4.y, 0.f);
                a4.z = fmaxf(a4.z, 0.f); a4.w = fmaxf(a4.w, 0.f);
            }
            int row = arow + hh * 64;
            As[0][acol + 0][row] = f2tf32(a4.x);
            As[0][acol + 1][row] = f2tf32(a4.y);
            As[0][acol + 2][row] = f2tf32(a4.z);
            As[0][acol + 3][row] = f2tf32(a4.w);
        }
#pragma unroll
        for (int nv = 0; nv < BN / 64; nv++) {
            int col = bcol + nv * 64;
            Bs[0][brow][col + 0] = f2tf32(br[nv].x);
            Bs[0][brow][col + 1] = f2tf32(br[nv].y);
            Bs[0][brow][col + 2] = f2tf32(br[nv].z);
            Bs[0][brow][col + 3] = f2tf32(br[nv].w);
        }
    }
    __syncthreads();

    int KT = K / BK;
    for (int kt = 0; kt < KT; kt++) {
        int cur = kt & 1;
        // prefetch next tile into registers
        if (kt + 1 < KT) {
            int k0 = (kt + 1) * BK;
#pragma unroll
            for (int hh = 0; hh < 2; hh++)
                ar[hh] = *(const float4*)&A[(size_t)(bm + arow + hh * 64) * K + k0 + acol];
#pragma unroll
            for (int nv = 0; nv < BN / 64; nv++)
                br[nv] = *(const float4*)&W[(size_t)(k0 + brow) * BN + bcol + nv * 64];
        }
        // compute on current buffer
#pragma unroll
        for (int ks = 0; ks < 2; ks++) {
            unsigned af[TM][4], bf[TN][2];
#pragma unroll
            for (int mi = 0; mi < TM; mi++) {
                int m = wm * WM + mi * 16 + lr;
                int k = ks * 8 + lc;
                af[mi][0] = As[cur][k][m];
                af[mi][1] = As[cur][k][m + 8];
                af[mi][2] = As[cur][k + 4][m];
                af[mi][3] = As[cur][k + 4][m + 8];
            }
#pragma unroll
            for (int ni = 0; ni < TN; ni++) {
                int n = wn * WN + ni * 8 + lr;
                bf[ni][0] = Bs[cur][ks * 8 + lc][n];
                bf[ni][1] = Bs[cur][ks * 8 + 4 + lc][n];
            }
#pragma unroll
            for (int mi = 0; mi < TM; mi++)
#pragma unroll
                for (int ni = 0; ni < TN; ni++) {
                    asm volatile(
                        "mma.sync.aligned.m16n8k8.row.col.f32.tf32.tf32.f32 "
                        "{%0,%1,%2,%3}, {%4,%5,%6,%7}, {%8,%9}, {%0,%1,%2,%3};"
                        : "+f"(acc[mi][ni][0]), "+f"(acc[mi][ni][1]),
                          "+f"(acc[mi][ni][2]), "+f"(acc[mi][ni][3])
                        : "r"(af[mi][0]), "r"(af[mi][1]), "r"(af[mi][2]), "r"(af[mi][3]),
                          "r"(bf[ni][0]), "r"(bf[ni][1]));
                }
        }
        // store prefetched tile into other buffer
        if (kt + 1 < KT) {
            int nxt = cur ^ 1;
#pragma unroll
            for (int hh = 0; hh < 2; hh++) {
                float4 a4 = ar[hh];
                if (RELU_A) {
                    a4.x = fmaxf(a4.x, 0.f); a4.y = fmaxf(a4.y, 0.f);
                    a4.z = fmaxf(a4.z, 0.f); a4.w = fmaxf(a4.w, 0.f);
                }
                int row = arow + hh * 64;
                As[nxt][acol + 0][row] = f2tf32(a4.x);
                As[nxt][acol + 1][row] = f2tf32(a4.y);
                As[nxt][acol + 2][row] = f2tf32(a4.z);
                As[nxt][acol + 3][row] = f2tf32(a4.w);
            }
#pragma unroll
            for (int nv = 0; nv < BN / 64; nv++) {
                int col = bcol + nv * 64;
                Bs[nxt][brow][col + 0] = f2tf32(br[nv].x);
                Bs[nxt][brow][col + 1] = f2tf32(br[nv].y);
                Bs[nxt][brow][col + 2] = f2tf32(br[nv].z);
                Bs[nxt][brow][col + 3] = f2tf32(br[nv].w);
            }
        }
        __syncthreads();
    }

    // epilogue
#pragma unroll
    for (int mi = 0; mi < TM; mi++)
#pragma unroll
        for (int ni = 0; ni < TN; ni++) {
            int n = wn * WN + ni * 8 + lc * 2;
            float bv0 = 0.f, bv1 = 0.f;
            if (BIAS) { bv0 = bias[n]; bv1 = bias[n + 1]; }
#pragma unroll
            for (int half = 0; half < 2; half++) {
                int m = bm + wm * WM + mi * 16 + lr + half * 8;
                float2* ptr = (float2*)&C[(size_t)m * BN + n];
                float v0 = acc[mi][ni][half * 2 + 0] + bv0;
                float v1 = acc[mi][ni][half * 2 + 1] + bv1;
                if (ACCUM) {
                    float2 c = *ptr;
                    v0 += c.x; v1 += c.y;
                }
                *ptr = make_float2(v0, v1);
            }
        }
}

// ---------------- pooling (gather, no atomics) ----------------
__global__ void k_poolmax() {
    int t = blockIdx.x * 256 + threadIdx.x;   // 3*NSEG*H
    int f = t & 127;
    int bin = (t >> 7) & (NSEG - 1);
    int pl = t >> 23;
    int cnt = g_bcnt[pl][bin];
    if (cnt == 0) return;                      // empty bins never gathered
    int off = g_boff[pl][bin];
    float m = -FLT_MAX;
    for (int j = 0; j < cnt; j++) {
        int pt = g_pts[pl][off + j];
        m = fmaxf(m, g_net[(size_t)pt * H + f]);
    }
    g_segmax[pl][(size_t)bin * H + f] = m;
}

__global__ void k_concat() {
    int t = blockIdx.x * 256 + threadIdx.x;   // BT*H
    int i = t >> 7, f = t & 127;
    float s = 0.0f;
#pragma unroll
    for (int pl = 0; pl < 3; pl++)
        s += g_segmax[pl][(size_t)g_idx[pl][i] * H + f];
    g_x[(size_t)i * H2 + f] = g_net[t];
    g_x[(size_t)i * H2 + H + f] = s;
}

// ---------------- final mean (gather) + transposed output ----------------
__global__ void k_mean() {
    int t = blockIdx.x * 256 + threadIdx.x;   // 3*NSEG*CDIM
    int ch = t & 63;
    int bin = (t >> 6) & (NSEG - 1);
    int pl = t >> 22;
    int cnt = g_bcnt[pl][bin];
    float s = 0.0f;
    if (cnt > 0) {
        int off = g_boff[pl][bin];
        for (int j = 0; j < cnt; j++) {
            int pt = g_pts[pl][off + j];
            s += g_c[(size_t)pt * CDIM + ch];
        }
        s /= (float)cnt;
    }
    g_mean[pl][(size_t)bin * CDIM + ch] = s;
}

// out layout: [plane][b][ch][pix]; in: g_mean[pl][(b*R2+pix)*64 + ch]
__global__ void k_outT(float* __restrict__ out) {
    __shared__ float tile[32][33];
    int pix0 = blockIdx.x * 32;
    int ch0 = blockIdx.y * 32;
    int pb = blockIdx.z;                  // pl*4 + b
    int pl = pb >> 2, b = pb & 3;
    int tx = threadIdx.x, ty = threadIdx.y;
#pragma unroll
    for (int i = ty; i < 32; i += 8)
        tile[i][tx] = g_mean[pl][(size_t)(b * R2_ + pix0 + i) * CDIM + ch0 + tx];
    __syncthreads();
#pragma unroll
    for (int i = ty; i < 32; i += 8)
        out[((size_t)pb * CDIM + ch0 + i) * R2_ + pix0 + tx] = tile[tx][i];
}

// ---------------- launcher ----------------
extern "C" void kernel_launch(void* const* d_in, const int* in_sizes, int n_in,
                              void* d_out, int out_size) {
    const float* p   = (const float*)d_in[0];
    const float* fw  = (const float*)d_in[1];
    const float* fb  = (const float*)d_in[2];
    const float* w0  = (const float*)d_in[3];   // [5,256,128]
    const float* b0  = (const float*)d_in[4];   // [5,128]
    const float* w1  = (const float*)d_in[5];   // [5,128,128]
    const float* b1  = (const float*)d_in[6];   // [5,128]
    const float* ws  = (const float*)d_in[7];   // [5,256,128]
    const float* fcw = (const float*)d_in[8];   // [128,64]
    const float* fcb = (const float*)d_in[9];   // [64]
    float* out = (float*)d_out;

    float *gx, *gh, *gn, *gc;
    cudaGetSymbolAddress((void**)&gx, g_x);
    cudaGetSymbolAddress((void**)&gh, g_hidden);
    cudaGetSymbolAddress((void**)&gn, g_net);
    cudaGetSymbolAddress((void**)&gc, g_c);

    // CSR build (indices are fixed for the whole forward pass)
    k_idx<<<BT / 256, 256>>>(p);
    k_zerobcnt<<<(3 * NSEG) / 256, 256>>>();
    k_count<<<BT / 256, 256>>>();
    k_scan<<<3, 1024>>>();
    k_scatter<<<BT / 256, 256>>>();

    k_fcpos<<<BT, 256>>>(p, fw, fb);

    for (int i = 0; i < NB; i++) {
        if (i > 0) {
            k_poolmax<<<(3 * NSEG * H) / 256, 256>>>();
            k_concat<<<(BT * H) / 256, 256>>>();
        }
        // hidden = relu(x) @ w0 + b0
        k_mma<128, true, false, true, 2, 4><<<BT / 128, 256>>>(
            gx, w0 + (size_t)i * H2 * H, b0 + (size_t)i * H, gh, BT, H2);
        // net = relu(hidden) @ w1 + b1
        k_mma<128, true, false, true, 2, 4><<<BT / 128, 256>>>(
            gh, w1 + (size_t)i * H * H, b1 + (size_t)i * H, gn, BT, H);
        // net += x @ ws
        k_mma<128, false, true, false, 2, 4><<<BT / 128, 256>>>(
            gx, ws + (size_t)i * H2 * H, nullptr, gn, BT, H2);
    }

    // c = net @ fc_c_w + fc_c_b
    k_mma<64, false, false, true, 4, 2><<<BT / 128, 256>>>(
        gn, fcw, fcb, gc, BT, H);

    k_mean<<<(3 * NSEG * CDIM) / 256, 256>>>();
    k_outT<<<dim3(R2_ / 32, CDIM / 32, 3 * B_), dim3(32, 8)>>>(out);
}

// round 3
// speedup vs baseline: 1.8122x; 1.1673x over previous
#include <cuda_runtime.h>
#include <float.h>
#include <math.h>

// ---------------- problem constants ----------------
#define B_    4
#define T_    32768
#define BT    (B_ * T_)          // 131072 points
#define RESO_ 128
#define R2_   (RESO_ * RESO_)    // 16384
#define NSEG  (B_ * R2_)         // 65536 segments
#define H     128
#define H2    256
#define CDIM  64
#define NB    5

// ---------------- scratch (device globals, no allocation) ----------------
__device__ int   g_idx[3][BT];            // flat segment index per plane
__device__ int   g_rank[3][BT];           // rank of point within its bin
__device__ int   g_bcnt[3][NSEG];         // points per bin
__device__ int   g_boff[3][NSEG];         // exclusive prefix offsets
__device__ int   g_bsum[3][32];           // per-chunk sums for scan
__device__ int   g_pts[3][BT];            // CSR point lists
__device__ float g_x[(size_t)BT * H2];    // resblock input (concat) / fc_pos out
__device__ float g_net[(size_t)BT * H];
__device__ float g_segmax[3][(size_t)NSEG * H];
__device__ float g_c[(size_t)BT * CDIM];
__device__ float g_mean[3][(size_t)NSEG * CDIM];

// ---------------- helpers ----------------
__device__ __forceinline__ int norm_bin(float v) {
    float u = v / 1.10001f + 0.5f;                // (1 + PADDING + 1e-5)
    u = fminf(fmaxf(u, 0.0f), 0.99999f);          // clip [0, 1-1e-5]
    int q = (int)(u * 128.0f);
    return q < 127 ? q : 127;
}

__device__ __forceinline__ unsigned f2tf32(float f) {
    unsigned u;
    asm("cvt.rna.tf32.f32 %0, %1;" : "=r"(u) : "f"(f));
    return u;
}

// ---------------- index / CSR build ----------------
__global__ void k_zerobcnt() {
    int t = blockIdx.x * 256 + threadIdx.x;   // 3*NSEG
    (&g_bcnt[0][0])[t] = 0;
}

__global__ void k_idxcount(const float* __restrict__ p) {
    int i = blockIdx.x * 256 + threadIdx.x;
    if (i >= BT) return;
    float x = p[3 * i + 0], y = p[3 * i + 1], z = p[3 * i + 2];
    int base = (i / T_) * R2_;
    int ix = norm_bin(x), iy = norm_bin(y), iz = norm_bin(z);
    int idx0 = base + ix + RESO_ * iz;  // xz
    int idx1 = base + ix + RESO_ * iy;  // xy
    int idx2 = base + iy + RESO_ * iz;  // yz
    g_idx[0][i] = idx0; g_idx[1][i] = idx1; g_idx[2][i] = idx2;
    g_rank[0][i] = atomicAdd(&g_bcnt[0][idx0], 1);
    g_rank[1][i] = atomicAdd(&g_bcnt[1][idx1], 1);
    g_rank[2][i] = atomicAdd(&g_bcnt[2][idx2], 1);
}

// two-level scan: 2048-elem chunks (32 chunks/plane)
__global__ void k_scanA() {
    int pl = blockIdx.y, chunk = blockIdx.x;
    int tid = threadIdx.x;
    int base = chunk * 2048 + tid * 2;
    int v0 = g_bcnt[pl][base], v1 = g_bcnt[pl][base + 1];
    int v = v0 + v1;
    int lane = tid & 31, wid = tid >> 5;
    int x = v;
#pragma unroll
    for (int o = 1; o < 32; o <<= 1) {
        int y = __shfl_up_sync(0xffffffffu, x, o);
        if (lane >= o) x += y;
    }
    __shared__ int wsum[32];
    if (lane == 31) wsum[wid] = x;
    __syncthreads();
    if (wid == 0) {
        int s = wsum[lane];
#pragma unroll
        for (int o = 1; o < 32; o <<= 1) {
            int y = __shfl_up_sync(0xffffffffu, s, o);
            if (lane >= o) s += y;
        }
        wsum[lane] = s;
    }
    __syncthreads();
    int incl = x + (wid ? wsum[wid - 1] : 0);
    int excl = incl - v;
    g_boff[pl][base] = excl;
    g_boff[pl][base + 1] = excl + v0;
    if (tid == 1023) g_bsum[pl][chunk] = incl;
}

__global__ void k_scanB() {   // 1 block, 96 threads: warp per plane
    int pl = threadIdx.x >> 5, lane = threadIdx.x & 31;
    int v = g_bsum[pl][lane];
    int x = v;
#pragma unroll
    for (int o = 1; o < 32; o <<= 1) {
        int y = __shfl_up_sync(0xffffffffu, x, o);
        if (lane >= o) x += y;
    }
    g_bsum[pl][lane] = x - v;   // exclusive
}

__global__ void k_scanC() {   // 192 blocks x 1024
    int t = blockIdx.x * 1024 + threadIdx.x;
    int pl = t >> 16;
    int g = t & (NSEG - 1);
    g_boff[pl][g] += g_bsum[pl][g >> 11];
}

__global__ void k_scatter() {
    int i = blockIdx.x * 256 + threadIdx.x;   // BT
#pragma unroll
    for (int pl = 0; pl < 3; pl++) {
        int bin = g_idx[pl][i];
        g_pts[pl][g_boff[pl][bin] + g_rank[pl][i]] = i;
    }
}

// ---------------- fc_pos (exact fp32) ----------------
__global__ void k_fcpos(const float* __restrict__ p,
                        const float* __restrict__ w,
                        const float* __restrict__ b) {
    int i = blockIdx.x;
    int j = threadIdx.x;
    float x0 = p[3 * i], x1 = p[3 * i + 1], x2 = p[3 * i + 2];
    g_x[(size_t)i * H2 + j] = x0 * w[j] + x1 * w[H2 + j] + x2 * w[2 * H2 + j] + b[j];
}

// ---------------- fused resblock kernel ----------------
// NET[64xBM tile,128] = X@ws + relu(relu(X)@w0 + b0)@w1 + b1
// BM=64, 256 threads (8 warps: 2x4), warp tile 32x32, thread 2x4 frags.
#define RB_ASR 72      // A / hidden row stride (mod 32 == 8 -> conflict-free)
#define RB_BSR 136     // B row stride
// smem u32 layout:
//   As  [2][16][72]   = 2304
//   B0s [2][16][136]  = 4352
//   BSs [2][16][136]  = 4352
//   Hs  [128][72]     = 9216
#define RB_AS(buf, k, m)  sm[(buf) * (16 * RB_ASR) + (k) * RB_ASR + (m)]
#define RB_B0(buf, k, n)  sm[2304 + (buf) * (16 * RB_BSR) + (k) * RB_BSR + (n)]
#define RB_BS(buf, k, n)  sm[6656 + (buf) * (16 * RB_BSR) + (k) * RB_BSR + (n)]
#define RB_HS(k, m)       sm[11008 + (k) * RB_ASR + (m)]
#define RB_SMEM_BYTES ((11008 + 128 * RB_ASR) * 4)

__global__ void __launch_bounds__(256)
k_resblock(const float* __restrict__ X,    // [BT,256]
           const float* __restrict__ w0,   // [256,128]
           const float* __restrict__ b0,   // [128]
           const float* __restrict__ w1,   // [128,128]
           const float* __restrict__ b1,   // [128]
           const float* __restrict__ ws,   // [256,128]
           float* __restrict__ NET) {      // [BT,128]
    extern __shared__ unsigned sm[];
    int tid = threadIdx.x;
    int bm = blockIdx.x * 64;
    int w = tid >> 5, lane = tid & 31;
    int wm = w & 1, wn = w >> 1;              // 2 x 4 warps
    int lr = lane >> 2, lc = lane & 3;

    int arow = tid >> 2;            // 0..63
    int acol = (tid & 3) * 4;       // 0,4,8,12
    int brow = tid >> 4;            // 0..15
    int bcol = (tid & 15) * 4;      // 0..60

    float accH[2][4][4];
    float accS[2][4][4];
#pragma unroll
    for (int mi = 0; mi < 2; mi++)
#pragma unroll
        for (int ni = 0; ni < 4; ni++)
#pragma unroll
            for (int q = 0; q < 4; q++) { accH[mi][ni][q] = 0.f; accS[mi][ni][q] = 0.f; }

    float4 ar, b0r[2], bsr[2];

    // ---- phase 1: K=256, accH = relu(X)@w0, accS = X@ws ----
    // prologue tile 0
    ar = *(const float4*)&X[(size_t)(bm + arow) * H2 + acol];
#pragma unroll
    for (int nv = 0; nv < 2; nv++) {
        b0r[nv] = *(const float4*)&w0[(size_t)brow * H + bcol + nv * 64];
        bsr[nv] = *(const float4*)&ws[(size_t)brow * H + bcol + nv * 64];
    }
    RB_AS(0, acol + 0, arow) = f2tf32(ar.x);
    RB_AS(0, acol + 1, arow) = f2tf32(ar.y);
    RB_AS(0, acol + 2, arow) = f2tf32(ar.z);
    RB_AS(0, acol + 3, arow) = f2tf32(ar.w);
#pragma unroll
    for (int nv = 0; nv < 2; nv++) {
        int col = bcol + nv * 64;
        RB_B0(0, brow, col + 0) = f2tf32(b0r[nv].x);
        RB_B0(0, brow, col + 1) = f2tf32(b0r[nv].y);
        RB_B0(0, brow, col + 2) = f2tf32(b0r[nv].z);
        RB_B0(0, brow, col + 3) = f2tf32(b0r[nv].w);
        RB_BS(0, brow, col + 0) = f2tf32(bsr[nv].x);
        RB_BS(0, brow, col + 1) = f2tf32(bsr[nv].y);
        RB_BS(0, brow, col + 2) = f2tf32(bsr[nv].z);
        RB_BS(0, brow, col + 3) = f2tf32(bsr[nv].w);
    }
    __syncthreads();

    for (int kt = 0; kt < 16; kt++) {
        int cur = kt & 1;
        if (kt + 1 < 16) {
            int k0 = (kt + 1) * 16;
            ar = *(const float4*)&X[(size_t)(bm + arow) * H2 + k0 + acol];
#pragma unroll
            for (int nv = 0; nv < 2; nv++) {
                b0r[nv] = *(const float4*)&w0[(size_t)(k0 + brow) * H + bcol + nv * 64];
                bsr[nv] = *(const float4*)&ws[(size_t)(k0 + brow) * H + bcol + nv * 64];
            }
        }
#pragma unroll
        for (int ks = 0; ks < 2; ks++) {
            unsigned afr[2][4], afh[2][4], bf0[4][2], bfs[4][2];
#pragma unroll
            for (int mi = 0; mi < 2; mi++) {
                int m = wm * 32 + mi * 16 + lr;
                int k = ks * 8 + lc;
                afr[mi][0] = RB_AS(cur, k, m);
                afr[mi][1] = RB_AS(cur, k, m + 8);
                afr[mi][2] = RB_AS(cur, k + 4, m);
                afr[mi][3] = RB_AS(cur, k + 4, m + 8);
#pragma unroll
                for (int q = 0; q < 4; q++)
                    afh[mi][q] = __float_as_uint(fmaxf(__uint_as_float(afr[mi][q]), 0.f));
            }
#pragma unroll
            for (int ni = 0; ni < 4; ni++) {
                int n = wn * 32 + ni * 8 + lr;
                bf0[ni][0] = RB_B0(cur, ks * 8 + lc, n);
                bf0[ni][1] = RB_B0(cur, ks * 8 + 4 + lc, n);
                bfs[ni][0] = RB_BS(cur, ks * 8 + lc, n);
                bfs[ni][1] = RB_BS(cur, ks * 8 + 4 + lc, n);
            }
#pragma unroll
            for (int mi = 0; mi < 2; mi++)
#pragma unroll
                for (int ni = 0; ni < 4; ni++) {
                    asm volatile(
                        "mma.sync.aligned.m16n8k8.row.col.f32.tf32.tf32.f32 "
                        "{%0,%1,%2,%3}, {%4,%5,%6,%7}, {%8,%9}, {%0,%1,%2,%3};"
                        : "+f"(accH[mi][ni][0]), "+f"(accH[mi][ni][1]),
                          "+f"(accH[mi][ni][2]), "+f"(accH[mi][ni][3])
                        : "r"(afh[mi][0]), "r"(afh[mi][1]), "r"(afh[mi][2]), "r"(afh[mi][3]),
                          "r"(bf0[ni][0]), "r"(bf0[ni][1]));
                    asm volatile(
                        "mma.sync.aligned.m16n8k8.row.col.f32.tf32.tf32.f32 "
                        "{%0,%1,%2,%3}, {%4,%5,%6,%7}, {%8,%9}, {%0,%1,%2,%3};"
                        : "+f"(accS[mi][ni][0]), "+f"(accS[mi][ni][1]),
                          "+f"(accS[mi][ni][2]), "+f"(accS[mi][ni][3])
                        : "r"(afr[mi][0]), "r"(afr[mi][1]), "r"(afr[mi][2]), "r"(afr[mi][3]),
                          "r"(bfs[ni][0]), "r"(bfs[ni][1]));
                }
        }
        if (kt + 1 < 16) {
            int nxt = cur ^ 1;
            RB_AS(nxt, acol + 0, arow) = f2tf32(ar.x);
            RB_AS(nxt, acol + 1, arow) = f2tf32(ar.y);
            RB_AS(nxt, acol + 2, arow) = f2tf32(ar.z);
            RB_AS(nxt, acol + 3, arow) = f2tf32(ar.w);
#pragma unroll
            for (int nv = 0; nv < 2; nv++) {
                int col = bcol + nv * 64;
                RB_B0(nxt, brow, col + 0) = f2tf32(b0r[nv].x);
                RB_B0(nxt, brow, col + 1) = f2tf32(b0r[nv].y);
                RB_B0(nxt, brow, col + 2) = f2tf32(b0r[nv].z);
                RB_B0(nxt, brow, col + 3) = f2tf32(b0r[nv].w);
                RB_BS(nxt, brow, col + 0) = f2tf32(bsr[nv].x);
                RB_BS(nxt, brow, col + 1) = f2tf32(bsr[nv].y);
                RB_BS(nxt, brow, col + 2) = f2tf32(bsr[nv].z);
                RB_BS(nxt, brow, col + 3) = f2tf32(bsr[nv].w);
            }
        }
        __syncthreads();
    }

    // ---- store Hs = relu(accH + b0)  (layout [n][m], tf32) ----
#pragma unroll
    for (int mi = 0; mi < 2; mi++)
#pragma unroll
        for (int ni = 0; ni < 4; ni++) {
            int n = wn * 32 + ni * 8 + lc * 2;
            float bv0 = b0[n], bv1 = b0[n + 1];
#pragma unroll
            for (int half = 0; half < 2; half++) {
                int m = wm * 32 + mi * 16 + lr + half * 8;
                RB_HS(n, m)     = f2tf32(fmaxf(accH[mi][ni][half * 2 + 0] + bv0, 0.f));
                RB_HS(n + 1, m) = f2tf32(fmaxf(accH[mi][ni][half * 2 + 1] + bv1, 0.f));
            }
        }
    // preload w1 tile 0 into B0s[0]
#pragma unroll
    for (int nv = 0; nv < 2; nv++)
        b0r[nv] = *(const float4*)&w1[(size_t)brow * H + bcol + nv * 64];
    __syncthreads();   // Hs visible; phase-1 B0s no longer read
#pragma unroll
    for (int nv = 0; nv < 2; nv++) {
        int col = bcol + nv * 64;
        RB_B0(0, brow, col + 0) = f2tf32(b0r[nv].x);
        RB_B0(0, brow, col + 1) = f2tf32(b0r[nv].y);
        RB_B0(0, brow, col + 2) = f2tf32(b0r[nv].z);
        RB_B0(0, brow, col + 3) = f2tf32(b0r[nv].w);
    }
    __syncthreads();

    // ---- phase 2: accS += Hs(=relu(hidden)) @ w1, K=128 ----
    for (int kt = 0; kt < 8; kt++) {
        int cur = kt & 1;
        if (kt + 1 < 8) {
            int k0 = (kt + 1) * 16;
#pragma unroll
            for (int nv = 0; nv < 2; nv++)
                b0r[nv] = *(const float4*)&w1[(size_t)(k0 + brow) * H + bcol + nv * 64];
        }
#pragma unroll
        for (int ks = 0; ks < 2; ks++) {
            unsigned af[2][4], bf[4][2];
            int kk = kt * 16 + ks * 8 + lc;
#pragma unroll
            for (int mi = 0; mi < 2; mi++) {
                int m = wm * 32 + mi * 16 + lr;
                af[mi][0] = RB_HS(kk, m);
                af[mi][1] = RB_HS(kk, m + 8);
                af[mi][2] = RB_HS(kk + 4, m);
                af[mi][3] = RB_HS(kk + 4, m + 8);
            }
#pragma unroll
            for (int ni = 0; ni < 4; ni++) {
                int n = wn * 32 + ni * 8 + lr;
                bf[ni][0] = RB_B0(cur, ks * 8 + lc, n);
                bf[ni][1] = RB_B0(cur, ks * 8 + 4 + lc, n);
            }
#pragma unroll
            for (int mi = 0; mi < 2; mi++)
#pragma unroll
                for (int ni = 0; ni < 4; ni++) {
                    asm volatile(
                        "mma.sync.aligned.m16n8k8.row.col.f32.tf32.tf32.f32 "
                        "{%0,%1,%2,%3}, {%4,%5,%6,%7}, {%8,%9}, {%0,%1,%2,%3};"
                        : "+f"(accS[mi][ni][0]), "+f"(accS[mi][ni][1]),
                          "+f"(accS[mi][ni][2]), "+f"(accS[mi][ni][3])
                        : "r"(af[mi][0]), "r"(af[mi][1]), "r"(af[mi][2]), "r"(af[mi][3]),
                          "r"(bf[ni][0]), "r"(bf[ni][1]));
                }
        }
        if (kt + 1 < 8) {
            int nxt = cur ^ 1;
#pragma unroll
            for (int nv = 0; nv < 2; nv++) {
                int col = bcol + nv * 64;
                RB_B0(nxt, brow, col + 0) = f2tf32(b0r[nv].x);
                RB_B0(nxt, brow, col + 1) = f2tf32(b0r[nv].y);
                RB_B0(nxt, brow, col + 2) = f2tf32(b0r[nv].z);
                RB_B0(nxt, brow, col + 3) = f2tf32(b0r[nv].w);
            }
        }
        __syncthreads();
    }

    // ---- epilogue: NET = accS + b1 ----
#pragma unroll
    for (int mi = 0; mi < 2; mi++)
#pragma unroll
        for (int ni = 0; ni < 4; ni++) {
            int n = wn * 32 + ni * 8 + lc * 2;
            float bv0 = b1[n], bv1 = b1[n + 1];
#pragma unroll
            for (int half = 0; half < 2; half++) {
                int m = bm + wm * 32 + mi * 16 + lr + half * 8;
                *(float2*)&NET[(size_t)m * H + n] =
                    make_float2(accS[mi][ni][half * 2 + 0] + bv0,
                                accS[mi][ni][half * 2 + 1] + bv1);
            }
        }
}

// ---------------- generic TF32 GEMM (used for fc_c) ----------------
template <int BN, bool RELU_A, bool ACCUM, bool BIAS, int WARPS_M, int WARPS_N>
__global__ void __launch_bounds__(256)
k_mma(const float* __restrict__ A, const float* __restrict__ W,
      const float* __restrict__ bias, float* __restrict__ C,
      int M, int K) {
    constexpr int BM = 128, BK = 16;
    constexpr int WM = BM / WARPS_M, WN = BN / WARPS_N;
    constexpr int TM = WM / 16, TN = WN / 8;
    constexpr int ASr = BM + 8, BSr = BN + 8;
    __shared__ unsigned As[2][BK][ASr];
    __shared__ unsigned Bs[2][BK][BSr];
    int tid = threadIdx.x;
    int bm = blockIdx.x * BM;
    int w = tid >> 5, lane = tid & 31;
    int wm = w % WARPS_M, wn = w / WARPS_M;
    int lr = lane >> 2, lc = lane & 3;

    float acc[TM][TN][4];
#pragma unroll
    for (int mi = 0; mi < TM; mi++)
#pragma unroll
        for (int ni = 0; ni < TN; ni++)
#pragma unroll
            for (int q = 0; q < 4; q++) acc[mi][ni][q] = 0.0f;

    int arow = tid >> 2;
    int acol = (tid & 3) * 4;
    int brow = tid >> 4;
    int bcol = (tid & 15) * 4;

    float4 ar[2];
    float4 br[(BN + 63) / 64];

    {
#pragma unroll
        for (int hh = 0; hh < 2; hh++)
            ar[hh] = *(const float4*)&A[(size_t)(bm + arow + hh * 64) * K + acol];
#pragma unroll
        for (int nv = 0; nv < (BN + 63) / 64 && bcol + nv * 64 < BN; nv++)
            br[nv] = *(const float4*)&W[(size_t)brow * BN + bcol + nv * 64];
#pragma unroll
        for (int hh = 0; hh < 2; hh++) {
            float4 a4 = ar[hh];
            if (RELU_A) {
                a4.x = fmaxf(a4.x, 0.f); a4.y = fmaxf(a4.y, 0.f);
                a4.z = fmaxf(a4.z, 0.f); a4.w = fmaxf(a4.w, 0.f);
            }
            int row = arow + hh * 64;
            As[0][acol + 0][row] = f2tf32(a4.x);
            As[0][acol + 1][row] = f2tf32(a4.y);
            As[0][acol + 2][row] = f2tf32(a4.z);
            As[0][acol + 3][row] = f2tf32(a4.w);
        }
#pragma unroll
        for (int nv = 0; nv < (BN + 63) / 64 && bcol + nv * 64 < BN; nv++) {
            int col = bcol + nv * 64;
            Bs[0][brow][col + 0] = f2tf32(br[nv].x);
            Bs[0][brow][col + 1] = f2tf32(br[nv].y);
            Bs[0][brow][col + 2] = f2tf32(br[nv].z);
            Bs[0][brow][col + 3] = f2tf32(br[nv].w);
        }
    }
    __syncthreads();

    int KT = K / BK;
    for (int kt = 0; kt < KT; kt++) {
        int cur = kt & 1;
        if (kt + 1 < KT) {
            int k0 = (kt + 1) * BK;
#pragma unroll
            for (int hh = 0; hh < 2; hh++)
                ar[hh] = *(const float4*)&A[(size_t)(bm + arow + hh * 64) * K + k0 + acol];
#pragma unroll
            for (int nv = 0; nv < (BN + 63) / 64 && bcol + nv * 64 < BN; nv++)
                br[nv] = *(const float4*)&W[(size_t)(k0 + brow) * BN + bcol + nv * 64];
        }
#pragma unroll
        for (int ks = 0; ks < 2; ks++) {
            unsigned af[TM][4], bf[TN][2];
#pragma unroll
            for (int mi = 0; mi < TM; mi++) {
                int m = wm * WM + mi * 16 + lr;
                int k = ks * 8 + lc;
                af[mi][0] = As[cur][k][m];
                af[mi][1] = As[cur][k][m + 8];
                af[mi][2] = As[cur][k + 4][m];
                af[mi][3] = As[cur][k + 4][m + 8];
            }
#pragma unroll
            for (int ni = 0; ni < TN; ni++) {
                int n = wn * WN + ni * 8 + lr;
                bf[ni][0] = Bs[cur][ks * 8 + lc][n];
                bf[ni][1] = Bs[cur][ks * 8 + 4 + lc][n];
            }
#pragma unroll
            for (int mi = 0; mi < TM; mi++)
#pragma unroll
                for (int ni = 0; ni < TN; ni++) {
                    asm volatile(
                        "mma.sync.aligned.m16n8k8.row.col.f32.tf32.tf32.f32 "
                        "{%0,%1,%2,%3}, {%4,%5,%6,%7}, {%8,%9}, {%0,%1,%2,%3};"
                        : "+f"(acc[mi][ni][0]), "+f"(acc[mi][ni][1]),
                          "+f"(acc[mi][ni][2]), "+f"(acc[mi][ni][3])
                        : "r"(af[mi][0]), "r"(af[mi][1]), "r"(af[mi][2]), "r"(af[mi][3]),
                          "r"(bf[ni][0]), "r"(bf[ni][1]));
                }
        }
        if (kt + 1 < KT) {
            int nxt = cur ^ 1;
#pragma unroll
            for (int hh = 0; hh < 2; hh++) {
                float4 a4 = ar[hh];
                if (RELU_A) {
                    a4.x = fmaxf(a4.x, 0.f); a4.y = fmaxf(a4.y, 0.f);
                    a4.z = fmaxf(a4.z, 0.f); a4.w = fmaxf(a4.w, 0.f);
                }
                int row = arow + hh * 64;
                As[nxt][acol + 0][row] = f2tf32(a4.x);
                As[nxt][acol + 1][row] = f2tf32(a4.y);
                As[nxt][acol + 2][row] = f2tf32(a4.z);
                As[nxt][acol + 3][row] = f2tf32(a4.w);
            }
#pragma unroll
            for (int nv = 0; nv < (BN + 63) / 64 && bcol + nv * 64 < BN; nv++) {
                int col = bcol + nv * 64;
                Bs[nxt][brow][col + 0] = f2tf32(br[nv].x);
                Bs[nxt][brow][col + 1] = f2tf32(br[nv].y);
                Bs[nxt][brow][col + 2] = f2tf32(br[nv].z);
                Bs[nxt][brow][col + 3] = f2tf32(br[nv].w);
            }
        }
        __syncthreads();
    }

#pragma unroll
    for (int mi = 0; mi < TM; mi++)
#pragma unroll
        for (int ni = 0; ni < TN; ni++) {
            int n = wn * WN + ni * 8 + lc * 2;
            float bv0 = 0.f, bv1 = 0.f;
            if (BIAS) { bv0 = bias[n]; bv1 = bias[n + 1]; }
#pragma unroll
            for (int half = 0; half < 2; half++) {
                int m = bm + wm * WM + mi * 16 + lr + half * 8;
                float2* ptr = (float2*)&C[(size_t)m * BN + n];
                float v0 = acc[mi][ni][half * 2 + 0] + bv0;
                float v1 = acc[mi][ni][half * 2 + 1] + bv1;
                if (ACCUM) {
                    float2 c = *ptr;
                    v0 += c.x; v1 += c.y;
                }
                *ptr = make_float2(v0, v1);
            }
        }
}

// ---------------- pooling (gather, no atomics) ----------------
__global__ void k_poolmax() {
    int t = blockIdx.x * 256 + threadIdx.x;   // 3*NSEG*H
    int f = t & 127;
    int bin = (t >> 7) & (NSEG - 1);
    int pl = t >> 23;
    int cnt = g_bcnt[pl][bin];
    if (cnt == 0) return;
    int off = g_boff[pl][bin];
    float m = -FLT_MAX;
    for (int j = 0; j < cnt; j++) {
        int pt = g_pts[pl][off + j];
        m = fmaxf(m, g_net[(size_t)pt * H + f]);
    }
    g_segmax[pl][(size_t)bin * H + f] = m;
}

__global__ void k_concat() {
    int t = blockIdx.x * 256 + threadIdx.x;   // BT*H
    int i = t >> 7, f = t & 127;
    float s = 0.0f;
#pragma unroll
    for (int pl = 0; pl < 3; pl++)
        s += g_segmax[pl][(size_t)g_idx[pl][i] * H + f];
    g_x[(size_t)i * H2 + f] = g_net[t];
    g_x[(size_t)i * H2 + H + f] = s;
}

// ---------------- final mean (gather) + transposed output ----------------
__global__ void k_mean() {
    int t = blockIdx.x * 256 + threadIdx.x;   // 3*NSEG*CDIM
    int ch = t & 63;
    int bin = (t >> 6) & (NSEG - 1);
    int pl = t >> 22;
    int cnt = g_bcnt[pl][bin];
    float s = 0.0f;
    if (cnt > 0) {
        int off = g_boff[pl][bin];
        for (int j = 0; j < cnt; j++) {
            int pt = g_pts[pl][off + j];
            s += g_c[(size_t)pt * CDIM + ch];
        }
        s /= (float)cnt;
    }
    g_mean[pl][(size_t)bin * CDIM + ch] = s;
}

__global__ void k_outT(float* __restrict__ out) {
    __shared__ float tile[32][33];
    int pix0 = blockIdx.x * 32;
    int ch0 = blockIdx.y * 32;
    int pb = blockIdx.z;                  // pl*4 + b
    int pl = pb >> 2, b = pb & 3;
    int tx = threadIdx.x, ty = threadIdx.y;
#pragma unroll
    for (int i = ty; i < 32; i += 8)
        tile[i][tx] = g_mean[pl][(size_t)(b * R2_ + pix0 + i) * CDIM + ch0 + tx];
    __syncthreads();
#pragma unroll
    for (int i = ty; i < 32; i += 8)
        out[((size_t)pb * CDIM + ch0 + i) * R2_ + pix0 + tx] = tile[tx][i];
}

// ---------------- launcher ----------------
extern "C" void kernel_launch(void* const* d_in, const int* in_sizes, int n_in,
                              void* d_out, int out_size) {
    const float* p   = (const float*)d_in[0];
    const float* fw  = (const float*)d_in[1];
    const float* fb  = (const float*)d_in[2];
    const float* w0  = (const float*)d_in[3];   // [5,256,128]
    const float* b0  = (const float*)d_in[4];   // [5,128]
    const float* w1  = (const float*)d_in[5];   // [5,128,128]
    const float* b1  = (const float*)d_in[6];   // [5,128]
    const float* ws  = (const float*)d_in[7];   // [5,256,128]
    const float* fcw = (const float*)d_in[8];   // [128,64]
    const float* fcb = (const float*)d_in[9];   // [64]
    float* out = (float*)d_out;

    float *gx, *gn, *gc;
    cudaGetSymbolAddress((void**)&gx, g_x);
    cudaGetSymbolAddress((void**)&gn, g_net);
    cudaGetSymbolAddress((void**)&gc, g_c);

    static bool attr_done = false;
    if (!attr_done) {
        cudaFuncSetAttribute(k_resblock,
                             cudaFuncAttributeMaxDynamicSharedMemorySize,
                             RB_SMEM_BYTES);
        attr_done = true;
    }

    // CSR build
    k_zerobcnt<<<(3 * NSEG) / 256, 256>>>();
    k_idxcount<<<BT / 256, 256>>>(p);
    k_scanA<<<dim3(32, 3), 1024>>>();
    k_scanB<<<1, 96>>>();
    k_scanC<<<192, 1024>>>();
    k_scatter<<<BT / 256, 256>>>();

    k_fcpos<<<BT, 256>>>(p, fw, fb);

    for (int i = 0; i < NB; i++) {
        if (i > 0) {
            k_poolmax<<<(3 * NSEG * H) / 256, 256>>>();
            k_concat<<<(BT * H) / 256, 256>>>();
        }
        k_resblock<<<BT / 64, 256, RB_SMEM_BYTES>>>(
            gx, w0 + (size_t)i * H2 * H, b0 + (size_t)i * H,
            w1 + (size_t)i * H * H, b1 + (size_t)i * H,
            ws + (size_t)i * H2 * H, gn);
    }

    // c = net @ fc_c_w + fc_c_b
    k_mma<64, false, false, true, 4, 2><<<BT / 128, 256>>>(gn, fcw, fcb, gc, BT, H);

    k_mean<<<(3 * NSEG * CDIM) / 256, 256>>>();
    k_outT<<<dim3(R2_ / 32, CDIM / 32, 3 * B_), dim3(32, 8)>>>(out);
}

// round 4
// speedup vs baseline: 2.9144x; 1.6082x over previous
#include <cuda_runtime.h>
#include <float.h>
#include <math.h>

// ---------------- problem constants ----------------
#define B_    4
#define T_    32768
#define BT    (B_ * T_)          // 131072 points
#define RESO_ 128
#define R2_   (RESO_ * RESO_)    // 16384
#define NSEG  (B_ * R2_)         // 65536 segments
#define H     128
#define H2    256
#define CDIM  64
#define NB    5

// ---------------- scratch (device globals, no allocation) ----------------
__device__ int   g_idx[3][BT];            // flat segment index per plane
__device__ int   g_rank[3][BT];           // rank of point within its bin
__device__ int   g_bcnt[3][NSEG];         // points per bin
__device__ int   g_boff[3][NSEG];         // exclusive prefix offsets
__device__ int   g_bsum[3][32];           // per-chunk sums for scan
__device__ int   g_pts[3][BT];            // CSR point lists
__device__ float g_net[(size_t)BT * H];
__device__ float g_segmax[3][(size_t)NSEG * H];
__device__ float g_c[(size_t)BT * CDIM];
__device__ float g_mean[3][(size_t)NSEG * CDIM];

// ---------------- helpers ----------------
__device__ __forceinline__ int norm_bin(float v) {
    float u = v / 1.10001f + 0.5f;                // (1 + PADDING + 1e-5)
    u = fminf(fmaxf(u, 0.0f), 0.99999f);          // clip [0, 1-1e-5]
    int q = (int)(u * 128.0f);
    return q < 127 ? q : 127;
}

__device__ __forceinline__ unsigned f2tf32(float f) {
    unsigned u;
    asm("cvt.rna.tf32.f32 %0, %1;" : "=r"(u) : "f"(f));
    return u;
}

// ---------------- index / CSR build ----------------
__global__ void k_zerobcnt() {
    int t = blockIdx.x * 256 + threadIdx.x;   // 3*NSEG
    (&g_bcnt[0][0])[t] = 0;
}

__global__ void k_idxcount(const float* __restrict__ p) {
    int i = blockIdx.x * 256 + threadIdx.x;
    if (i >= BT) return;
    float x = p[3 * i + 0], y = p[3 * i + 1], z = p[3 * i + 2];
    int base = (i / T_) * R2_;
    int ix = norm_bin(x), iy = norm_bin(y), iz = norm_bin(z);
    int idx0 = base + ix + RESO_ * iz;  // xz
    int idx1 = base + ix + RESO_ * iy;  // xy
    int idx2 = base + iy + RESO_ * iz;  // yz
    g_idx[0][i] = idx0; g_idx[1][i] = idx1; g_idx[2][i] = idx2;
    g_rank[0][i] = atomicAdd(&g_bcnt[0][idx0], 1);
    g_rank[1][i] = atomicAdd(&g_bcnt[1][idx1], 1);
    g_rank[2][i] = atomicAdd(&g_bcnt[2][idx2], 1);
}

// two-level scan: 2048-elem chunks (32 chunks/plane)
__global__ void k_scanA() {
    int pl = blockIdx.y, chunk = blockIdx.x;
    int tid = threadIdx.x;
    int base = chunk * 2048 + tid * 2;
    int v0 = g_bcnt[pl][base], v1 = g_bcnt[pl][base + 1];
    int v = v0 + v1;
    int lane = tid & 31, wid = tid >> 5;
    int x = v;
#pragma unroll
    for (int o = 1; o < 32; o <<= 1) {
        int y = __shfl_up_sync(0xffffffffu, x, o);
        if (lane >= o) x += y;
    }
    __shared__ int wsum[32];
    if (lane == 31) wsum[wid] = x;
    __syncthreads();
    if (wid == 0) {
        int s = wsum[lane];
#pragma unroll
        for (int o = 1; o < 32; o <<= 1) {
            int y = __shfl_up_sync(0xffffffffu, s, o);
            if (lane >= o) s += y;
        }
        wsum[lane] = s;
    }
    __syncthreads();
    int incl = x + (wid ? wsum[wid - 1] : 0);
    int excl = incl - v;
    g_boff[pl][base] = excl;
    g_boff[pl][base + 1] = excl + v0;
    if (tid == 1023) g_bsum[pl][chunk] = incl;
}

__global__ void k_scanB() {   // 1 block, 96 threads: warp per plane
    int pl = threadIdx.x >> 5, lane = threadIdx.x & 31;
    int v = g_bsum[pl][lane];
    int x = v;
#pragma unroll
    for (int o = 1; o < 32; o <<= 1) {
        int y = __shfl_up_sync(0xffffffffu, x, o);
        if (lane >= o) x += y;
    }
    g_bsum[pl][lane] = x - v;   // exclusive
}

__global__ void k_scanC() {   // 192 blocks x 1024
    int t = blockIdx.x * 1024 + threadIdx.x;
    int pl = t >> 16;
    int g = t & (NSEG - 1);
    g_boff[pl][g] += g_bsum[pl][g >> 11];
}

__global__ void k_scatter() {
    int i = blockIdx.x * 256 + threadIdx.x;   // BT
#pragma unroll
    for (int pl = 0; pl < 3; pl++) {
        int bin = g_idx[pl][i];
        g_pts[pl][g_boff[pl][bin] + g_rank[pl][i]] = i;
    }
}

// ---------------- fused resblock kernel ----------------
// MODE 0: X = fc_pos(p) computed inline.
// MODE 1: X = [net | sum3 segmax(idx)] gathered inline.
// NET[64-row tile,128] = X@ws + relu(relu(X)@w0 + b0)@w1 + b1
// BM=64, 256 threads (8 warps: 2x4), warp tile 32x32.
#define RB_ASR 72      // stride mod 32 == 8 -> conflict-free
#define RB_BSR 136
#define RB_AS(buf, k, m)  sm[(buf) * (16 * RB_ASR) + (k) * RB_ASR + (m)]
#define RB_B0(buf, k, n)  sm[2304 + (buf) * (16 * RB_BSR) + (k) * RB_BSR + (n)]
#define RB_BS(buf, k, n)  sm[6656 + (buf) * (16 * RB_BSR) + (k) * RB_BSR + (n)]
#define RB_HS(k, m)       sm[11008 + (k) * RB_ASR + (m)]
#define RB_SMEM_BYTES ((11008 + 128 * RB_ASR) * 4)

template <int MODE>
__global__ void __launch_bounds__(256)
k_resblock(const float* __restrict__ P,    // MODE 0: [BT,3]
           const float* __restrict__ FW,   // MODE 0: [3,256]
           const float* __restrict__ FB,   // MODE 0: [256]
           const float* __restrict__ w0,   // [256,128]
           const float* __restrict__ b0,   // [128]
           const float* __restrict__ w1,   // [128,128]
           const float* __restrict__ b1,   // [128]
           const float* __restrict__ ws,   // [256,128]
           float* __restrict__ NET) {      // [BT,128] (in-place safe)
    extern __shared__ unsigned sm[];
    int tid = threadIdx.x;
    int bm = blockIdx.x * 64;
    int w = tid >> 5, lane = tid & 31;
    int wm = w & 1, wn = w >> 1;              // 2 x 4 warps
    int lr = lane >> 2, lc = lane & 3;

    int arow = tid >> 2;            // 0..63
    int acol = (tid & 3) * 4;       // 0,4,8,12
    int brow = tid >> 4;            // 0..15
    int bcol = (tid & 15) * 4;      // 0..60

    // per-row state for A synthesis
    int row = bm + arow;
    float p0, p1, p2;
    int ix0, ix1, ix2;
    if (MODE == 0) {
        p0 = P[3 * row]; p1 = P[3 * row + 1]; p2 = P[3 * row + 2];
    } else {
        ix0 = g_idx[0][row]; ix1 = g_idx[1][row]; ix2 = g_idx[2][row];
    }

    float accH[2][4][4];
    float accS[2][4][4];
#pragma unroll
    for (int mi = 0; mi < 2; mi++)
#pragma unroll
        for (int ni = 0; ni < 4; ni++)
#pragma unroll
            for (int q = 0; q < 4; q++) { accH[mi][ni][q] = 0.f; accS[mi][ni][q] = 0.f; }

    float4 ar, b0r[2], bsr[2];

    // synthesize A[row, k0+acol .. +3]
    auto loadA = [&](int k0) -> float4 {
        int col = k0 + acol;
        if (MODE == 0) {
            float4 wa = *(const float4*)&FW[col];
            float4 wb = *(const float4*)&FW[H2 + col];
            float4 wc = *(const float4*)&FW[2 * H2 + col];
            float4 bb = *(const float4*)&FB[col];
            return make_float4(p0 * wa.x + p1 * wb.x + p2 * wc.x + bb.x,
                               p0 * wa.y + p1 * wb.y + p2 * wc.y + bb.y,
                               p0 * wa.z + p1 * wb.z + p2 * wc.z + bb.z,
                               p0 * wa.w + p1 * wb.w + p2 * wc.w + bb.w);
        } else {
            if (col < H) {   // uniform per k-tile
                return *(const float4*)&NET[(size_t)row * H + col];
            } else {
                int c2 = col - H;
                float4 a = *(const float4*)&g_segmax[0][(size_t)ix0 * H + c2];
                float4 b = *(const float4*)&g_segmax[1][(size_t)ix1 * H + c2];
                float4 c = *(const float4*)&g_segmax[2][(size_t)ix2 * H + c2];
                return make_float4(a.x + b.x + c.x, a.y + b.y + c.y,
                                   a.z + b.z + c.z, a.w + b.w + c.w);
            }
        }
    };

    // ---- phase 1: K=256, accH = relu(X)@w0, accS = X@ws ----
    ar = loadA(0);
#pragma unroll
    for (int nv = 0; nv < 2; nv++) {
        b0r[nv] = *(const float4*)&w0[(size_t)brow * H + bcol + nv * 64];
        bsr[nv] = *(const float4*)&ws[(size_t)brow * H + bcol + nv * 64];
    }
    RB_AS(0, acol + 0, arow) = f2tf32(ar.x);
    RB_AS(0, acol + 1, arow) = f2tf32(ar.y);
    RB_AS(0, acol + 2, arow) = f2tf32(ar.z);
    RB_AS(0, acol + 3, arow) = f2tf32(ar.w);
#pragma unroll
    for (int nv = 0; nv < 2; nv++) {
        int col = bcol + nv * 64;
        RB_B0(0, brow, col + 0) = f2tf32(b0r[nv].x);
        RB_B0(0, brow, col + 1) = f2tf32(b0r[nv].y);
        RB_B0(0, brow, col + 2) = f2tf32(b0r[nv].z);
        RB_B0(0, brow, col + 3) = f2tf32(b0r[nv].w);
        RB_BS(0, brow, col + 0) = f2tf32(bsr[nv].x);
        RB_BS(0, brow, col + 1) = f2tf32(bsr[nv].y);
        RB_BS(0, brow, col + 2) = f2tf32(bsr[nv].z);
        RB_BS(0, brow, col + 3) = f2tf32(bsr[nv].w);
    }
    __syncthreads();

    for (int kt = 0; kt < 16; kt++) {
        int cur = kt & 1;
        if (kt + 1 < 16) {
            int k0 = (kt + 1) * 16;
            ar = loadA(k0);
#pragma unroll
            for (int nv = 0; nv < 2; nv++) {
                b0r[nv] = *(const float4*)&w0[(size_t)(k0 + brow) * H + bcol + nv * 64];
                bsr[nv] = *(const float4*)&ws[(size_t)(k0 + brow) * H + bcol + nv * 64];
            }
        }
#pragma unroll
        for (int ks = 0; ks < 2; ks++) {
            unsigned afr[2][4], afh[2][4], bf0[4][2], bfs[4][2];
#pragma unroll
            for (int mi = 0; mi < 2; mi++) {
                int m = wm * 32 + mi * 16 + lr;
                int k = ks * 8 + lc;
                afr[mi][0] = RB_AS(cur, k, m);
                afr[mi][1] = RB_AS(cur, k, m + 8);
                afr[mi][2] = RB_AS(cur, k + 4, m);
                afr[mi][3] = RB_AS(cur, k + 4, m + 8);
#pragma unroll
                for (int q = 0; q < 4; q++)
                    afh[mi][q] = __float_as_uint(fmaxf(__uint_as_float(afr[mi][q]), 0.f));
            }
#pragma unroll
            for (int ni = 0; ni < 4; ni++) {
                int n = wn * 32 + ni * 8 + lr;
                bf0[ni][0] = RB_B0(cur, ks * 8 + lc, n);
                bf0[ni][1] = RB_B0(cur, ks * 8 + 4 + lc, n);
                bfs[ni][0] = RB_BS(cur, ks * 8 + lc, n);
                bfs[ni][1] = RB_BS(cur, ks * 8 + 4 + lc, n);
            }
#pragma unroll
            for (int mi = 0; mi < 2; mi++)
#pragma unroll
                for (int ni = 0; ni < 4; ni++) {
                    asm volatile(
                        "mma.sync.aligned.m16n8k8.row.col.f32.tf32.tf32.f32 "
                        "{%0,%1,%2,%3}, {%4,%5,%6,%7}, {%8,%9}, {%0,%1,%2,%3};"
                        : "+f"(accH[mi][ni][0]), "+f"(accH[mi][ni][1]),
                          "+f"(accH[mi][ni][2]), "+f"(accH[mi][ni][3])
                        : "r"(afh[mi][0]), "r"(afh[mi][1]), "r"(afh[mi][2]), "r"(afh[mi][3]),
                          "r"(bf0[ni][0]), "r"(bf0[ni][1]));
                    asm volatile(
                        "mma.sync.aligned.m16n8k8.row.col.f32.tf32.tf32.f32 "
                        "{%0,%1,%2,%3}, {%4,%5,%6,%7}, {%8,%9}, {%0,%1,%2,%3};"
                        : "+f"(accS[mi][ni][0]), "+f"(accS[mi][ni][1]),
                          "+f"(accS[mi][ni][2]), "+f"(accS[mi][ni][3])
                        : "r"(afr[mi][0]), "r"(afr[mi][1]), "r"(afr[mi][2]), "r"(afr[mi][3]),
                          "r"(bfs[ni][0]), "r"(bfs[ni][1]));
                }
        }
        if (kt + 1 < 16) {
            int nxt = cur ^ 1;
            RB_AS(nxt, acol + 0, arow) = f2tf32(ar.x);
            RB_AS(nxt, acol + 1, arow) = f2tf32(ar.y);
            RB_AS(nxt, acol + 2, arow) = f2tf32(ar.z);
            RB_AS(nxt, acol + 3, arow) = f2tf32(ar.w);
#pragma unroll
            for (int nv = 0; nv < 2; nv++) {
                int col = bcol + nv * 64;
                RB_B0(nxt, brow, col + 0) = f2tf32(b0r[nv].x);
                RB_B0(nxt, brow, col + 1) = f2tf32(b0r[nv].y);
                RB_B0(nxt, brow, col + 2) = f2tf32(b0r[nv].z);
                RB_B0(nxt, brow, col + 3) = f2tf32(b0r[nv].w);
                RB_BS(nxt, brow, col + 0) = f2tf32(bsr[nv].x);
                RB_BS(nxt, brow, col + 1) = f2tf32(bsr[nv].y);
                RB_BS(nxt, brow, col + 2) = f2tf32(bsr[nv].z);
                RB_BS(nxt, brow, col + 3) = f2tf32(bsr[nv].w);
            }
        }
        __syncthreads();
    }

    // ---- store Hs = relu(accH + b0)  (layout [n][m], tf32) ----
#pragma unroll
    for (int mi = 0; mi < 2; mi++)
#pragma unroll
        for (int ni = 0; ni < 4; ni++) {
            int n = wn * 32 + ni * 8 + lc * 2;
            float bv0 = b0[n], bv1 = b0[n + 1];
#pragma unroll
            for (int half = 0; half < 2; half++) {
                int m = wm * 32 + mi * 16 + lr + half * 8;
                RB_HS(n, m)     = f2tf32(fmaxf(accH[mi][ni][half * 2 + 0] + bv0, 0.f));
                RB_HS(n + 1, m) = f2tf32(fmaxf(accH[mi][ni][half * 2 + 1] + bv1, 0.f));
            }
        }
#pragma unroll
    for (int nv = 0; nv < 2; nv++)
        b0r[nv] = *(const float4*)&w1[(size_t)brow * H + bcol + nv * 64];
    __syncthreads();
#pragma unroll
    for (int nv = 0; nv < 2; nv++) {
        int col = bcol + nv * 64;
        RB_B0(0, brow, col + 0) = f2tf32(b0r[nv].x);
        RB_B0(0, brow, col + 1) = f2tf32(b0r[nv].y);
        RB_B0(0, brow, col + 2) = f2tf32(b0r[nv].z);
        RB_B0(0, brow, col + 3) = f2tf32(b0r[nv].w);
    }
    __syncthreads();

    // ---- phase 2: accS += Hs(=relu(hidden)) @ w1, K=128 ----
    for (int kt = 0; kt < 8; kt++) {
        int cur = kt & 1;
        if (kt + 1 < 8) {
            int k0 = (kt + 1) * 16;
#pragma unroll
            for (int nv = 0; nv < 2; nv++)
                b0r[nv] = *(const float4*)&w1[(size_t)(k0 + brow) * H + bcol + nv * 64];
        }
#pragma unroll
        for (int ks = 0; ks < 2; ks++) {
            unsigned af[2][4], bf[4][2];
            int kk = kt * 16 + ks * 8 + lc;
#pragma unroll
            for (int mi = 0; mi < 2; mi++) {
                int m = wm * 32 + mi * 16 + lr;
                af[mi][0] = RB_HS(kk, m);
                af[mi][1] = RB_HS(kk, m + 8);
                af[mi][2] = RB_HS(kk + 4, m);
                af[mi][3] = RB_HS(kk + 4, m + 8);
            }
#pragma unroll
            for (int ni = 0; ni < 4; ni++) {
                int n = wn * 32 + ni * 8 + lr;
                bf[ni][0] = RB_B0(cur, ks * 8 + lc, n);
                bf[ni][1] = RB_B0(cur, ks * 8 + 4 + lc, n);
            }
#pragma unroll
            for (int mi = 0; mi < 2; mi++)
#pragma unroll
                for (int ni = 0; ni < 4; ni++) {
                    asm volatile(
                        "mma.sync.aligned.m16n8k8.row.col.f32.tf32.tf32.f32 "
                        "{%0,%1,%2,%3}, {%4,%5,%6,%7}, {%8,%9}, {%0,%1,%2,%3};"
                        : "+f"(accS[mi][ni][0]), "+f"(accS[mi][ni][1]),
                          "+f"(accS[mi][ni][2]), "+f"(accS[mi][ni][3])
                        : "r"(af[mi][0]), "r"(af[mi][1]), "r"(af[mi][2]), "r"(af[mi][3]),
                          "r"(bf[ni][0]), "r"(bf[ni][1]));
                }
        }
        if (kt + 1 < 8) {
            int nxt = cur ^ 1;
#pragma unroll
            for (int nv = 0; nv < 2; nv++) {
                int col = bcol + nv * 64;
                RB_B0(nxt, brow, col + 0) = f2tf32(b0r[nv].x);
                RB_B0(nxt, brow, col + 1) = f2tf32(b0r[nv].y);
                RB_B0(nxt, brow, col + 2) = f2tf32(b0r[nv].z);
                RB_B0(nxt, brow, col + 3) = f2tf32(b0r[nv].w);
            }
        }
        __syncthreads();
    }

    // ---- epilogue: NET = accS + b1 ----
#pragma unroll
    for (int mi = 0; mi < 2; mi++)
#pragma unroll
        for (int ni = 0; ni < 4; ni++) {
            int n = wn * 32 + ni * 8 + lc * 2;
            float bv0 = b1[n], bv1 = b1[n + 1];
#pragma unroll
            for (int half = 0; half < 2; half++) {
                int m = bm + wm * 32 + mi * 16 + lr + half * 8;
                *(float2*)&NET[(size_t)m * H + n] =
                    make_float2(accS[mi][ni][half * 2 + 0] + bv0,
                                accS[mi][ni][half * 2 + 1] + bv1);
            }
        }
}

// ---------------- generic TF32 GEMM (used for fc_c) ----------------
template <int BN, bool RELU_A, bool ACCUM, bool BIAS, int WARPS_M, int WARPS_N>
__global__ void __launch_bounds__(256)
k_mma(const float* __restrict__ A, const float* __restrict__ W,
      const float* __restrict__ bias, float* __restrict__ C,
      int M, int K) {
    constexpr int BM = 128, BK = 16;
    constexpr int WM = BM / WARPS_M, WN = BN / WARPS_N;
    constexpr int TM = WM / 16, TN = WN / 8;
    constexpr int ASr = BM + 8, BSr = BN + 8;
    __shared__ unsigned As[2][BK][ASr];
    __shared__ unsigned Bs[2][BK][BSr];
    int tid = threadIdx.x;
    int bm = blockIdx.x * BM;
    int w = tid >> 5, lane = tid & 31;
    int wm = w % WARPS_M, wn = w / WARPS_M;
    int lr = lane >> 2, lc = lane & 3;

    float acc[TM][TN][4];
#pragma unroll
    for (int mi = 0; mi < TM; mi++)
#pragma unroll
        for (int ni = 0; ni < TN; ni++)
#pragma unroll
            for (int q = 0; q < 4; q++) acc[mi][ni][q] = 0.0f;

    int arow = tid >> 2;
    int acol = (tid & 3) * 4;
    int brow = tid >> 4;
    int bcol = (tid & 15) * 4;

    float4 ar[2];
    float4 br[(BN + 63) / 64];

    {
#pragma unroll
        for (int hh = 0; hh < 2; hh++)
            ar[hh] = *(const float4*)&A[(size_t)(bm + arow + hh * 64) * K + acol];
#pragma unroll
        for (int nv = 0; nv < (BN + 63) / 64 && bcol + nv * 64 < BN; nv++)
            br[nv] = *(const float4*)&W[(size_t)brow * BN + bcol + nv * 64];
#pragma unroll
        for (int hh = 0; hh < 2; hh++) {
            float4 a4 = ar[hh];
            if (RELU_A) {
                a4.x = fmaxf(a4.x, 0.f); a4.y = fmaxf(a4.y, 0.f);
                a4.z = fmaxf(a4.z, 0.f); a4.w = fmaxf(a4.w, 0.f);
            }
            int row = arow + hh * 64;
            As[0][acol + 0][row] = f2tf32(a4.x);
            As[0][acol + 1][row] = f2tf32(a4.y);
            As[0][acol + 2][row] = f2tf32(a4.z);
            As[0][acol + 3][row] = f2tf32(a4.w);
        }
#pragma unroll
        for (int nv = 0; nv < (BN + 63) / 64 && bcol + nv * 64 < BN; nv++) {
            int col = bcol + nv * 64;
            Bs[0][brow][col + 0] = f2tf32(br[nv].x);
            Bs[0][brow][col + 1] = f2tf32(br[nv].y);
            Bs[0][brow][col + 2] = f2tf32(br[nv].z);
            Bs[0][brow][col + 3] = f2tf32(br[nv].w);
        }
    }
    __syncthreads();

    int KT = K / BK;
    for (int kt = 0; kt < KT; kt++) {
        int cur = kt & 1;
        if (kt + 1 < KT) {
            int k0 = (kt + 1) * BK;
#pragma unroll
            for (int hh = 0; hh < 2; hh++)
                ar[hh] = *(const float4*)&A[(size_t)(bm + arow + hh * 64) * K + k0 + acol];
#pragma unroll
            for (int nv = 0; nv < (BN + 63) / 64 && bcol + nv * 64 < BN; nv++)
                br[nv] = *(const float4*)&W[(size_t)(k0 + brow) * BN + bcol + nv * 64];
        }
#pragma unroll
        for (int ks = 0; ks < 2; ks++) {
            unsigned af[TM][4], bf[TN][2];
#pragma unroll
            for (int mi = 0; mi < TM; mi++) {
                int m = wm * WM + mi * 16 + lr;
                int k = ks * 8 + lc;
                af[mi][0] = As[cur][k][m];
                af[mi][1] = As[cur][k][m + 8];
                af[mi][2] = As[cur][k + 4][m];
                af[mi][3] = As[cur][k + 4][m + 8];
            }
#pragma unroll
            for (int ni = 0; ni < TN; ni++) {
                int n = wn * WN + ni * 8 + lr;
                bf[ni][0] = Bs[cur][ks * 8 + lc][n];
                bf[ni][1] = Bs[cur][ks * 8 + 4 + lc][n];
            }
#pragma unroll
            for (int mi = 0; mi < TM; mi++)
#pragma unroll
                for (int ni = 0; ni < TN; ni++) {
                    asm volatile(
                        "mma.sync.aligned.m16n8k8.row.col.f32.tf32.tf32.f32 "
                        "{%0,%1,%2,%3}, {%4,%5,%6,%7}, {%8,%9}, {%0,%1,%2,%3};"
                        : "+f"(acc[mi][ni][0]), "+f"(acc[mi][ni][1]),
                          "+f"(acc[mi][ni][2]), "+f"(acc[mi][ni][3])
                        : "r"(af[mi][0]), "r"(af[mi][1]), "r"(af[mi][2]), "r"(af[mi][3]),
                          "r"(bf[ni][0]), "r"(bf[ni][1]));
                }
        }
        if (kt + 1 < KT) {
            int nxt = cur ^ 1;
#pragma unroll
            for (int hh = 0; hh < 2; hh++) {
                float4 a4 = ar[hh];
                if (RELU_A) {
                    a4.x = fmaxf(a4.x, 0.f); a4.y = fmaxf(a4.y, 0.f);
                    a4.z = fmaxf(a4.z, 0.f); a4.w = fmaxf(a4.w, 0.f);
                }
                int row = arow + hh * 64;
                As[nxt][acol + 0][row] = f2tf32(a4.x);
                As[nxt][acol + 1][row] = f2tf32(a4.y);
                As[nxt][acol + 2][row] = f2tf32(a4.z);
                As[nxt][acol + 3][row] = f2tf32(a4.w);
            }
#pragma unroll
            for (int nv = 0; nv < (BN + 63) / 64 && bcol + nv * 64 < BN; nv++) {
                int col = bcol + nv * 64;
                Bs[nxt][brow][col + 0] = f2tf32(br[nv].x);
                Bs[nxt][brow][col + 1] = f2tf32(br[nv].y);
                Bs[nxt][brow][col + 2] = f2tf32(br[nv].z);
                Bs[nxt][brow][col + 3] = f2tf32(br[nv].w);
            }
        }
        __syncthreads();
    }

#pragma unroll
    for (int mi = 0; mi < TM; mi++)
#pragma unroll
        for (int ni = 0; ni < TN; ni++) {
            int n = wn * WN + ni * 8 + lc * 2;
            float bv0 = 0.f, bv1 = 0.f;
            if (BIAS) { bv0 = bias[n]; bv1 = bias[n + 1]; }
#pragma unroll
            for (int half = 0; half < 2; half++) {
                int m = bm + wm * WM + mi * 16 + lr + half * 8;
                float2* ptr = (float2*)&C[(size_t)m * BN + n];
                float v0 = acc[mi][ni][half * 2 + 0] + bv0;
                float v1 = acc[mi][ni][half * 2 + 1] + bv1;
                if (ACCUM) {
                    float2 c = *ptr;
                    v0 += c.x; v1 += c.y;
                }
                *ptr = make_float2(v0, v1);
            }
        }
}

// ---------------- pooling (gather, float4) ----------------
__global__ void k_poolmax4() {
    int t = blockIdx.x * 256 + threadIdx.x;   // 3*NSEG*32
    int f4 = t & 31;
    int bin = (t >> 5) & (NSEG - 1);
    int pl = t >> 21;
    int cnt = g_bcnt[pl][bin];
    if (cnt == 0) return;
    int off = g_boff[pl][bin];
    float4 m = make_float4(-FLT_MAX, -FLT_MAX, -FLT_MAX, -FLT_MAX);
    for (int j = 0; j < cnt; j++) {
        int pt = g_pts[pl][off + j];
        float4 v = *(const float4*)&g_net[(size_t)pt * H + f4 * 4];
        m.x = fmaxf(m.x, v.x); m.y = fmaxf(m.y, v.y);
        m.z = fmaxf(m.z, v.z); m.w = fmaxf(m.w, v.w);
    }
    *(float4*)&g_segmax[pl][(size_t)bin * H + f4 * 4] = m;
}

// ---------------- final mean (gather, float4) + transposed output ----------------
__global__ void k_mean4() {
    int t = blockIdx.x * 256 + threadIdx.x;   // 3*NSEG*16
    int c4 = t & 15;
    int bin = (t >> 4) & (NSEG - 1);
    int pl = t >> 20;
    int cnt = g_bcnt[pl][bin];
    float4 s = make_float4(0.f, 0.f, 0.f, 0.f);
    if (cnt > 0) {
        int off = g_boff[pl][bin];
        for (int j = 0; j < cnt; j++) {
            int pt = g_pts[pl][off + j];
            float4 v = *(const float4*)&g_c[(size_t)pt * CDIM + c4 * 4];
            s.x += v.x; s.y += v.y; s.z += v.z; s.w += v.w;
        }
        float inv = 1.0f / (float)cnt;
        s.x *= inv; s.y *= inv; s.z *= inv; s.w *= inv;
    }
    *(float4*)&g_mean[pl][(size_t)bin * CDIM + c4 * 4] = s;
}

__global__ void k_outT(float* __restrict__ out) {
    __shared__ float tile[32][33];
    int pix0 = blockIdx.x * 32;
    int ch0 = blockIdx.y * 32;
    int pb = blockIdx.z;                  // pl*4 + b
    int pl = pb >> 2, b = pb & 3;
    int tx = threadIdx.x, ty = threadIdx.y;
#pragma unroll
    for (int i = ty; i < 32; i += 8)
        tile[i][tx] = g_mean[pl][(size_t)(b * R2_ + pix0 + i) * CDIM + ch0 + tx];
    __syncthreads();
#pragma unroll
    for (int i = ty; i < 32; i += 8)
        out[((size_t)pb * CDIM + ch0 + i) * R2_ + pix0 + tx] = tile[tx][i];
}

// ---------------- launcher ----------------
extern "C" void kernel_launch(void* const* d_in, const int* in_sizes, int n_in,
                              void* d_out, int out_size) {
    const float* p   = (const float*)d_in[0];
    const float* fw  = (const float*)d_in[1];
    const float* fb  = (const float*)d_in[2];
    const float* w0  = (const float*)d_in[3];   // [5,256,128]
    const float* b0  = (const float*)d_in[4];   // [5,128]
    const float* w1  = (const float*)d_in[5];   // [5,128,128]
    const float* b1  = (const float*)d_in[6];   // [5,128]
    const float* ws  = (const float*)d_in[7];   // [5,256,128]
    const float* fcw = (const float*)d_in[8];   // [128,64]
    const float* fcb = (const float*)d_in[9];   // [64]
    float* out = (float*)d_out;

    float *gn, *gc;
    cudaGetSymbolAddress((void**)&gn, g_net);
    cudaGetSymbolAddress((void**)&gc, g_c);

    static bool attr_done = false;
    if (!attr_done) {
        cudaFuncSetAttribute(k_resblock<0>,
                             cudaFuncAttributeMaxDynamicSharedMemorySize, RB_SMEM_BYTES);
        cudaFuncSetAttribute(k_resblock<1>,
                             cudaFuncAttributeMaxDynamicSharedMemorySize, RB_SMEM_BYTES);
        attr_done = true;
    }

    // CSR build
    k_zerobcnt<<<(3 * NSEG) / 256, 256>>>();
    k_idxcount<<<BT / 256, 256>>>(p);
    k_scanA<<<dim3(32, 3), 1024>>>();
    k_scanB<<<1, 96>>>();
    k_scanC<<<192, 1024>>>();
    k_scatter<<<BT / 256, 256>>>();

    // block 0: fc_pos fused
    k_resblock<0><<<BT / 64, 256, RB_SMEM_BYTES>>>(
        p, fw, fb, w0, b0, w1, b1, ws, gn);

    for (int i = 1; i < NB; i++) {
        k_poolmax4<<<(3 * NSEG * 32) / 256, 256>>>();
        k_resblock<1><<<BT / 64, 256, RB_SMEM_BYTES>>>(
            nullptr, nullptr, nullptr,
            w0 + (size_t)i * H2 * H, b0 + (size_t)i * H,
            w1 + (size_t)i * H * H, b1 + (size_t)i * H,
            ws + (size_t)i * H2 * H, gn);
    }

    // c = net @ fc_c_w + fc_c_b
    k_mma<64, false, false, true, 4, 2><<<BT / 128, 256>>>(gn, fcw, fcb, gc, BT, H);

    k_mean4<<<(3 * NSEG * 16) / 256, 256>>>();
    k_outT<<<dim3(R2_ / 32, CDIM / 32, 3 * B_), dim3(32, 8)>>>(out);
}

// round 6
// speedup vs baseline: 2.9405x; 1.0089x over previous
#include <cuda_runtime.h>
#include <cuda_fp16.h>
#include <float.h>
#include <math.h>

// ---------------- problem constants ----------------
#define B_    4
#define T_    32768
#define BT    (B_ * T_)          // 131072 points
#define RESO_ 128
#define R2_   (RESO_ * RESO_)    // 16384
#define NSEG  (B_ * R2_)         // 65536 segments
#define H     128
#define H2    256
#define CDIM  64
#define NB    5

// ---------------- scratch (device globals, no allocation) ----------------
__device__ int    g_idx[3][BT];
__device__ int    g_rank[3][BT];
__device__ int    g_bcnt[3][NSEG];
__device__ int    g_boff[3][NSEG];        // chunk-local exclusive offsets
__device__ int    g_bsum[3][32];          // exclusive chunk base offsets
__device__ int    g_pts[3][BT];
__device__ float  g_net[(size_t)BT * H];
__device__ __align__(16) __half g_segmax[3][(size_t)NSEG * H];
__device__ float  g_c[(size_t)BT * CDIM];

// ---------------- helpers ----------------
__device__ __forceinline__ int norm_bin(float v) {
    float u = v / 1.10001f + 0.5f;
    u = fminf(fmaxf(u, 0.0f), 0.99999f);
    int q = (int)(u * 128.0f);
    return q < 127 ? q : 127;
}

__device__ __forceinline__ unsigned f2tf32(float f) {
    unsigned u;
    asm("cvt.rna.tf32.f32 %0, %1;" : "=r"(u) : "f"(f));
    return u;
}

// ---------------- index / CSR build ----------------
__global__ void k_zerobcnt() {
    int t = blockIdx.x * 256 + threadIdx.x;   // 3*NSEG
    (&g_bcnt[0][0])[t] = 0;
}

__global__ void k_idxcount(const float* __restrict__ p) {
    int i = blockIdx.x * 256 + threadIdx.x;
    if (i >= BT) return;
    float x = p[3 * i + 0], y = p[3 * i + 1], z = p[3 * i + 2];
    int base = (i / T_) * R2_;
    int ix = norm_bin(x), iy = norm_bin(y), iz = norm_bin(z);
    int idx0 = base + ix + RESO_ * iz;
    int idx1 = base + ix + RESO_ * iy;
    int idx2 = base + iy + RESO_ * iz;
    g_idx[0][i] = idx0; g_idx[1][i] = idx1; g_idx[2][i] = idx2;
    g_rank[0][i] = atomicAdd(&g_bcnt[0][idx0], 1);
    g_rank[1][i] = atomicAdd(&g_bcnt[1][idx1], 1);
    g_rank[2][i] = atomicAdd(&g_bcnt[2][idx2], 1);
}

__global__ void k_scanA() {       // 2048-elem chunks, 32 chunks/plane
    int pl = blockIdx.y, chunk = blockIdx.x;
    int tid = threadIdx.x;
    int base = chunk * 2048 + tid * 2;
    int v0 = g_bcnt[pl][base], v1 = g_bcnt[pl][base + 1];
    int v = v0 + v1;
    int lane = tid & 31, wid = tid >> 5;
    int x = v;
#pragma unroll
    for (int o = 1; o < 32; o <<= 1) {
        int y = __shfl_up_sync(0xffffffffu, x, o);
        if (lane >= o) x += y;
    }
    __shared__ int wsum[32];
    if (lane == 31) wsum[wid] = x;
    __syncthreads();
    if (wid == 0) {
        int s = wsum[lane];
#pragma unroll
        for (int o = 1; o < 32; o <<= 1) {
            int y = __shfl_up_sync(0xffffffffu, s, o);
            if (lane >= o) s += y;
        }
        wsum[lane] = s;
    }
    __syncthreads();
    int incl = x + (wid ? wsum[wid - 1] : 0);
    int excl = incl - v;
    g_boff[pl][base] = excl;
    g_boff[pl][base + 1] = excl + v0;
    if (tid == 1023) g_bsum[pl][chunk] = incl;
}

__global__ void k_scanB() {       // 1 block, 96 threads: warp per plane
    int pl = threadIdx.x >> 5, lane = threadIdx.x & 31;
    int v = g_bsum[pl][lane];
    int x = v;
#pragma unroll
    for (int o = 1; o < 32; o <<= 1) {
        int y = __shfl_up_sync(0xffffffffu, x, o);
        if (lane >= o) x += y;
    }
    g_bsum[pl][lane] = x - v;     // exclusive chunk base
}

__global__ void k_scatter() {
    int i = blockIdx.x * 256 + threadIdx.x;   // BT
#pragma unroll
    for (int pl = 0; pl < 3; pl++) {
        int bin = g_idx[pl][i];
        int off = g_boff[pl][bin] + g_bsum[pl][bin >> 11];
        g_pts[pl][off + g_rank[pl][i]] = i;
    }
}

// ---------------- fused resblock kernel (BM=128, 256 threads) ----------------
// MODE 0: X = fc_pos(p) inline.  MODE 1: X = [net | sum3 segmax(idx)] inline.
// NET[tile,128] = X@ws + relu(relu(X)@w0 + b0)@w1 + b1
// 8 warps (wm 2 x wn 4), warp tile 64x32, TM=4, TN=4.
#define RB_SR 136      // stride mod 32 == 8 -> conflict-free fragment loads
#define RB_AS(buf, k, m)  sm[(buf) * (16 * RB_SR) + (k) * RB_SR + (m)]
#define RB_B0(buf, k, n)  sm[4352 + (buf) * (16 * RB_SR) + (k) * RB_SR + (n)]
#define RB_BS(buf, k, n)  sm[8704 + (buf) * (16 * RB_SR) + (k) * RB_SR + (n)]
#define RB_HS(k, m)       sm[13056 + (k) * RB_SR + (m)]
#define RB_SMEM_BYTES ((13056 + 128 * RB_SR) * 4)   // 121856 B

template <int MODE>
__global__ void __launch_bounds__(256)
k_resblock(const float* __restrict__ P,    // MODE 0: [BT,3]
           const float* __restrict__ FW,   // MODE 0: [3,256]
           const float* __restrict__ FB,   // MODE 0: [256]
           const float* __restrict__ w0,   // [256,128]
           const float* __restrict__ b0,   // [128]
           const float* __restrict__ w1,   // [128,128]
           const float* __restrict__ b1,   // [128]
           const float* __restrict__ ws,   // [256,128]
           float* __restrict__ NET) {      // [BT,128] (in-place safe)
    extern __shared__ unsigned sm[];
    int tid = threadIdx.x;
    int bm = blockIdx.x * 128;
    int w = tid >> 5, lane = tid & 31;
    int wm = w & 1, wn = w >> 1;              // 2 x 4
    int lr = lane >> 2, lc = lane & 3;

    int arow = tid >> 2;            // 0..63, handles rows arow, arow+64
    int acol = (tid & 3) * 4;
    int brow = tid >> 4;            // 0..15
    int bcol = (tid & 15) * 4;      // 0..60

    // per-row state for A synthesis (2 rows per thread)
    float pr[2][3];
    int ixr[2][3];
#pragma unroll
    for (int hh = 0; hh < 2; hh++) {
        int row = bm + arow + hh * 64;
        if (MODE == 0) {
            pr[hh][0] = P[3 * row]; pr[hh][1] = P[3 * row + 1]; pr[hh][2] = P[3 * row + 2];
        } else {
            ixr[hh][0] = g_idx[0][row]; ixr[hh][1] = g_idx[1][row]; ixr[hh][2] = g_idx[2][row];
        }
    }

    float accH[4][4][4];
    float accS[4][4][4];
#pragma unroll
    for (int mi = 0; mi < 4; mi++)
#pragma unroll
        for (int ni = 0; ni < 4; ni++)
#pragma unroll
            for (int q = 0; q < 4; q++) { accH[mi][ni][q] = 0.f; accS[mi][ni][q] = 0.f; }

    float4 ar[2], b0r[2], bsr[2];

    auto loadA = [&](int k0, int hh) -> float4 {
        int col = k0 + acol;
        if (MODE == 0) {
            float4 wa = *(const float4*)&FW[col];
            float4 wb = *(const float4*)&FW[H2 + col];
            float4 wc = *(const float4*)&FW[2 * H2 + col];
            float4 bb = *(const float4*)&FB[col];
            float q0 = pr[hh][0], q1 = pr[hh][1], q2 = pr[hh][2];
            return make_float4(q0 * wa.x + q1 * wb.x + q2 * wc.x + bb.x,
                               q0 * wa.y + q1 * wb.y + q2 * wc.y + bb.y,
                               q0 * wa.z + q1 * wb.z + q2 * wc.z + bb.z,
                               q0 * wa.w + q1 * wb.w + q2 * wc.w + bb.w);
        } else {
            if (col < H) {   // uniform per k-tile
                int row = bm + arow + hh * 64;
                return *(const float4*)&NET[(size_t)row * H + col];
            } else {
                int c2 = col - H;
                uint2 ua = *(const uint2*)&g_segmax[0][(size_t)ixr[hh][0] * H + c2];
                uint2 ub = *(const uint2*)&g_segmax[1][(size_t)ixr[hh][1] * H + c2];
                uint2 uc = *(const uint2*)&g_segmax[2][(size_t)ixr[hh][2] * H + c2];
                float2 a0 = __half22float2(*(__half2*)&ua.x), a1 = __half22float2(*(__half2*)&ua.y);
                float2 e0 = __half22float2(*(__half2*)&ub.x), e1 = __half22float2(*(__half2*)&ub.y);
                float2 c0 = __half22float2(*(__half2*)&uc.x), c1 = __half22float2(*(__half2*)&uc.y);
                return make_float4(a0.x + e0.x + c0.x, a0.y + e0.y + c0.y,
                                   a1.x + e1.x + c1.x, a1.y + e1.y + c1.y);
            }
        }
    };

    // ---- phase 1: K=256, accH = relu(X)@w0, accS = X@ws ----
#pragma unroll
    for (int hh = 0; hh < 2; hh++) ar[hh] = loadA(0, hh);
#pragma unroll
    for (int nv = 0; nv < 2; nv++) {
        b0r[nv] = *(const float4*)&w0[(size_t)brow * H + bcol + nv * 64];
        bsr[nv] = *(const float4*)&ws[(size_t)brow * H + bcol + nv * 64];
    }
#pragma unroll
    for (int hh = 0; hh < 2; hh++) {
        int row = arow + hh * 64;
        RB_AS(0, acol + 0, row) = f2tf32(ar[hh].x);
        RB_AS(0, acol + 1, row) = f2tf32(ar[hh].y);
        RB_AS(0, acol + 2, row) = f2tf32(ar[hh].z);
        RB_AS(0, acol + 3, row) = f2tf32(ar[hh].w);
    }
#pragma unroll
    for (int nv = 0; nv < 2; nv++) {
        int col = bcol + nv * 64;
        RB_B0(0, brow, col + 0) = f2tf32(b0r[nv].x);
        RB_B0(0, brow, col + 1) = f2tf32(b0r[nv].y);
        RB_B0(0, brow, col + 2) = f2tf32(b0r[nv].z);
        RB_B0(0, brow, col + 3) = f2tf32(b0r[nv].w);
        RB_BS(0, brow, col + 0) = f2tf32(bsr[nv].x);
        RB_BS(0, brow, col + 1) = f2tf32(bsr[nv].y);
        RB_BS(0, brow, col + 2) = f2tf32(bsr[nv].z);
        RB_BS(0, brow, col + 3) = f2tf32(bsr[nv].w);
    }
    __syncthreads();

    for (int kt = 0; kt < 16; kt++) {
        int cur = kt & 1;
        if (kt + 1 < 16) {
            int k0 = (kt + 1) * 16;
#pragma unroll
            for (int hh = 0; hh < 2; hh++) ar[hh] = loadA(k0, hh);
#pragma unroll
            for (int nv = 0; nv < 2; nv++) {
                b0r[nv] = *(const float4*)&w0[(size_t)(k0 + brow) * H + bcol + nv * 64];
                bsr[nv] = *(const float4*)&ws[(size_t)(k0 + brow) * H + bcol + nv * 64];
            }
        }
#pragma unroll
        for (int ks = 0; ks < 2; ks++) {
            unsigned afr[4][4], afh[4][4], bf0[4][2], bfs[4][2];
#pragma unroll
            for (int mi = 0; mi < 4; mi++) {
                int m = wm * 64 + mi * 16 + lr;
                int k = ks * 8 + lc;
                afr[mi][0] = RB_AS(cur, k, m);
                afr[mi][1] = RB_AS(cur, k, m + 8);
                afr[mi][2] = RB_AS(cur, k + 4, m);
                afr[mi][3] = RB_AS(cur, k + 4, m + 8);
#pragma unroll
                for (int q = 0; q < 4; q++)
                    afh[mi][q] = __float_as_uint(fmaxf(__uint_as_float(afr[mi][q]), 0.f));
            }
#pragma unroll
            for (int ni = 0; ni < 4; ni++) {
                int n = wn * 32 + ni * 8 + lr;
                bf0[ni][0] = RB_B0(cur, ks * 8 + lc, n);
                bf0[ni][1] = RB_B0(cur, ks * 8 + 4 + lc, n);
                bfs[ni][0] = RB_BS(cur, ks * 8 + lc, n);
                bfs[ni][1] = RB_BS(cur, ks * 8 + 4 + lc, n);
            }
#pragma unroll
            for (int mi = 0; mi < 4; mi++)
#pragma unroll
                for (int ni = 0; ni < 4; ni++) {
                    asm volatile(
                        "mma.sync.aligned.m16n8k8.row.col.f32.tf32.tf32.f32 "
                        "{%0,%1,%2,%3}, {%4,%5,%6,%7}, {%8,%9}, {%0,%1,%2,%3};"
                        : "+f"(accH[mi][ni][0]), "+f"(accH[mi][ni][1]),
                          "+f"(accH[mi][ni][2]), "+f"(accH[mi][ni][3])
                        : "r"(afh[mi][0]), "r"(afh[mi][1]), "r"(afh[mi][2]), "r"(afh[mi][3]),
                          "r"(bf0[ni][0]), "r"(bf0[ni][1]));
                    asm volatile(
                        "mma.sync.aligned.m16n8k8.row.col.f32.tf32.tf32.f32 "
                        "{%0,%1,%2,%3}, {%4,%5,%6,%7}, {%8,%9}, {%0,%1,%2,%3};"
                        : "+f"(accS[mi][ni][0]), "+f"(accS[mi][ni][1]),
                          "+f"(accS[mi][ni][2]), "+f"(accS[mi][ni][3])
                        : "r"(afr[mi][0]), "r"(afr[mi][1]), "r"(afr[mi][2]), "r"(afr[mi][3]),
                          "r"(bfs[ni][0]), "r"(bfs[ni][1]));
                }
        }
        if (kt + 1 < 16) {
            int nxt = cur ^ 1;
#pragma unroll
            for (int hh = 0; hh < 2; hh++) {
                int row = arow + hh * 64;
                RB_AS(nxt, acol + 0, row) = f2tf32(ar[hh].x);
                RB_AS(nxt, acol + 1, row) = f2tf32(ar[hh].y);
                RB_AS(nxt, acol + 2, row) = f2tf32(ar[hh].z);
                RB_AS(nxt, acol + 3, row) = f2tf32(ar[hh].w);
            }
#pragma unroll
            for (int nv = 0; nv < 2; nv++) {
                int col = bcol + nv * 64;
                RB_B0(nxt, brow, col + 0) = f2tf32(b0r[nv].x);
                RB_B0(nxt, brow, col + 1) = f2tf32(b0r[nv].y);
                RB_B0(nxt, brow, col + 2) = f2tf32(b0r[nv].z);
                RB_B0(nxt, brow, col + 3) = f2tf32(b0r[nv].w);
                RB_BS(nxt, brow, col + 0) = f2tf32(bsr[nv].x);
                RB_BS(nxt, brow, col + 1) = f2tf32(bsr[nv].y);
                RB_BS(nxt, brow, col + 2) = f2tf32(bsr[nv].z);
                RB_BS(nxt, brow, col + 3) = f2tf32(bsr[nv].w);
            }
        }
        __syncthreads();
    }

    // ---- store Hs = relu(accH + b0) (layout [n][m], tf32) ----
#pragma unroll
    for (int mi = 0; mi < 4; mi++)
#pragma unroll
        for (int ni = 0; ni < 4; ni++) {
            int n = wn * 32 + ni * 8 + lc * 2;
            float bv0 = b0[n], bv1 = b0[n + 1];
#pragma unroll
            for (int half = 0; half < 2; half++) {
                int m = wm * 64 + mi * 16 + lr + half * 8;
                RB_HS(n, m)     = f2tf32(fmaxf(accH[mi][ni][half * 2 + 0] + bv0, 0.f));
                RB_HS(n + 1, m) = f2tf32(fmaxf(accH[mi][ni][half * 2 + 1] + bv1, 0.f));
            }
        }
#pragma unroll
    for (int nv = 0; nv < 2; nv++)
        b0r[nv] = *(const float4*)&w1[(size_t)brow * H + bcol + nv * 64];
    __syncthreads();   // Hs visible; phase-1 B0s dead
#pragma unroll
    for (int nv = 0; nv < 2; nv++) {
        int col = bcol + nv * 64;
        RB_B0(0, brow, col + 0) = f2tf32(b0r[nv].x);
        RB_B0(0, brow, col + 1) = f2tf32(b0r[nv].y);
        RB_B0(0, brow, col + 2) = f2tf32(b0r[nv].z);
        RB_B0(0, brow, col + 3) = f2tf32(b0r[nv].w);
    }
    __syncthreads();

    // ---- phase 2: accS += Hs @ w1, K=128 ----
    for (int kt = 0; kt < 8; kt++) {
        int cur = kt & 1;
        if (kt + 1 < 8) {
            int k0 = (kt + 1) * 16;
#pragma unroll
            for (int nv = 0; nv < 2; nv++)
                b0r[nv] = *(const float4*)&w1[(size_t)(k0 + brow) * H + bcol + nv * 64];
        }
#pragma unroll
        for (int ks = 0; ks < 2; ks++) {
            unsigned af[4][4], bf[4][2];
            int kk = kt * 16 + ks * 8 + lc;
#pragma unroll
            for (int mi = 0; mi < 4; mi++) {
                int m = wm * 64 + mi * 16 + lr;
                af[mi][0] = RB_HS(kk, m);
                af[mi][1] = RB_HS(kk, m + 8);
                af[mi][2] = RB_HS(kk + 4, m);
                af[mi][3] = RB_HS(kk + 4, m + 8);
            }
#pragma unroll
            for (int ni = 0; ni < 4; ni++) {
                int n = wn * 32 + ni * 8 + lr;
                bf[ni][0] = RB_B0(cur, ks * 8 + lc, n);
                bf[ni][1] = RB_B0(cur, ks * 8 + 4 + lc, n);
            }
#pragma unroll
            for (int mi = 0; mi < 4; mi++)
#pragma unroll
                for (int ni = 0; ni < 4; ni++) {
                    asm volatile(
                        "mma.sync.aligned.m16n8k8.row.col.f32.tf32.tf32.f32 "
                        "{%0,%1,%2,%3}, {%4,%5,%6,%7}, {%8,%9}, {%0,%1,%2,%3};"
                        : "+f"(accS[mi][ni][0]), "+f"(accS[mi][ni][1]),
                          "+f"(accS[mi][ni][2]), "+f"(accS[mi][ni][3])
                        : "r"(af[mi][0]), "r"(af[mi][1]), "r"(af[mi][2]), "r"(af[mi][3]),
                          "r"(bf[ni][0]), "r"(bf[ni][1]));
                }
        }
        if (kt + 1 < 8) {
            int nxt = cur ^ 1;
#pragma unroll
            for (int nv = 0; nv < 2; nv++) {
                int col = bcol + nv * 64;
                RB_B0(nxt, brow, col + 0) = f2tf32(b0r[nv].x);
                RB_B0(nxt, brow, col + 1) = f2tf32(b0r[nv].y);
                RB_B0(nxt, brow, col + 2) = f2tf32(b0r[nv].z);
                RB_B0(nxt, brow, col + 3) = f2tf32(b0r[nv].w);
            }
        }
        __syncthreads();
    }

    // ---- epilogue: NET = accS + b1 ----
#pragma unroll
    for (int mi = 0; mi < 4; mi++)
#pragma unroll
        for (int ni = 0; ni < 4; ni++) {
            int n = wn * 32 + ni * 8 + lc * 2;
            float bv0 = b1[n], bv1 = b1[n + 1];
#pragma unroll
            for (int half = 0; half < 2; half++) {
                int m = bm + wm * 64 + mi * 16 + lr + half * 8;
                *(float2*)&NET[(size_t)m * H + n] =
                    make_float2(accS[mi][ni][half * 2 + 0] + bv0,
                                accS[mi][ni][half * 2 + 1] + bv1);
            }
        }
}

// ---------------- generic TF32 GEMM (fc_c) ----------------
template <int BN, bool BIAS, int WARPS_M, int WARPS_N>
__global__ void __launch_bounds__(256)
k_mma(const float* __restrict__ A, const float* __restrict__ W,
      const float* __restrict__ bias, float* __restrict__ C,
      int M, int K) {
    constexpr int BM = 128, BK = 16;
    constexpr int WM = BM / WARPS_M, WN = BN / WARPS_N;
    constexpr int TM = WM / 16, TN = WN / 8;
    constexpr int ASr = BM + 8, BSr = BN + 8;
    __shared__ unsigned As[2][BK][ASr];
    __shared__ unsigned Bs[2][BK][BSr];
    int tid = threadIdx.x;
    int bm = blockIdx.x * BM;
    int w = tid >> 5, lane = tid & 31;
    int wm = w % WARPS_M, wn = w / WARPS_M;
    int lr = lane >> 2, lc = lane & 3;

    float acc[TM][TN][4];
#pragma unroll
    for (int mi = 0; mi < TM; mi++)
#pragma unroll
        for (int ni = 0; ni < TN; ni++)
#pragma unroll
            for (int q = 0; q < 4; q++) acc[mi][ni][q] = 0.0f;

    int arow = tid >> 2;
    int acol = (tid & 3) * 4;
    int brow = tid >> 4;
    int bcol = (tid & 15) * 4;

    float4 ar[2];
    float4 br;

    {
#pragma unroll
        for (int hh = 0; hh < 2; hh++)
            ar[hh] = *(const float4*)&A[(size_t)(bm + arow + hh * 64) * K + acol];
        br = *(const float4*)&W[(size_t)brow * BN + bcol];
#pragma unroll
        for (int hh = 0; hh < 2; hh++) {
            int row = arow + hh * 64;
            As[0][acol + 0][row] = f2tf32(ar[hh].x);
            As[0][acol + 1][row] = f2tf32(ar[hh].y);
            As[0][acol + 2][row] = f2tf32(ar[hh].z);
            As[0][acol + 3][row] = f2tf32(ar[hh].w);
        }
        Bs[0][brow][bcol + 0] = f2tf32(br.x);
        Bs[0][brow][bcol + 1] = f2tf32(br.y);
        Bs[0][brow][bcol + 2] = f2tf32(br.z);
        Bs[0][brow][bcol + 3] = f2tf32(br.w);
    }
    __syncthreads();

    int KT = K / BK;
    for (int kt = 0; kt < KT; kt++) {
        int cur = kt & 1;
        if (kt + 1 < KT) {
            int k0 = (kt + 1) * BK;
#pragma unroll
            for (int hh = 0; hh < 2; hh++)
                ar[hh] = *(const float4*)&A[(size_t)(bm + arow + hh * 64) * K + k0 + acol];
            br = *(const float4*)&W[(size_t)(k0 + brow) * BN + bcol];
        }
#pragma unroll
        for (int ks = 0; ks < 2; ks++) {
            unsigned af[TM][4], bf[TN][2];
#pragma unroll
            for (int mi = 0; mi < TM; mi++) {
                int m = wm * WM + mi * 16 + lr;
                int k = ks * 8 + lc;
                af[mi][0] = As[cur][k][m];
                af[mi][1] = As[cur][k][m + 8];
                af[mi][2] = As[cur][k + 4][m];
                af[mi][3] = As[cur][k + 4][m + 8];
            }
#pragma unroll
            for (int ni = 0; ni < TN; ni++) {
                int n = wn * WN + ni * 8 + lr;
                bf[ni][0] = Bs[cur][ks * 8 + lc][n];
                bf[ni][1] = Bs[cur][ks * 8 + 4 + lc][n];
            }
#pragma unroll
            for (int mi = 0; mi < TM; mi++)
#pragma unroll
                for (int ni = 0; ni < TN; ni++) {
                    asm volatile(
                        "mma.sync.aligned.m16n8k8.row.col.f32.tf32.tf32.f32 "
                        "{%0,%1,%2,%3}, {%4,%5,%6,%7}, {%8,%9}, {%0,%1,%2,%3};"
                        : "+f"(acc[mi][ni][0]), "+f"(acc[mi][ni][1]),
                          "+f"(acc[mi][ni][2]), "+f"(acc[mi][ni][3])
                        : "r"(af[mi][0]), "r"(af[mi][1]), "r"(af[mi][2]), "r"(af[mi][3]),
                          "r"(bf[ni][0]), "r"(bf[ni][1]));
                }
        }
        if (kt + 1 < KT) {
            int nxt = cur ^ 1;
#pragma unroll
            for (int hh = 0; hh < 2; hh++) {
                int row = arow + hh * 64;
                As[nxt][acol + 0][row] = f2tf32(ar[hh].x);
                As[nxt][acol + 1][row] = f2tf32(ar[hh].y);
                As[nxt][acol + 2][row] = f2tf32(ar[hh].z);
                As[nxt][acol + 3][row] = f2tf32(ar[hh].w);
            }
            Bs[nxt][brow][bcol + 0] = f2tf32(br.x);
            Bs[nxt][brow][bcol + 1] = f2tf32(br.y);
            Bs[nxt][brow][bcol + 2] = f2tf32(br.z);
            Bs[nxt][brow][bcol + 3] = f2tf32(br.w);
        }
        __syncthreads();
    }

#pragma unroll
    for (int mi = 0; mi < TM; mi++)
#pragma unroll
        for (int ni = 0; ni < TN; ni++) {
            int n = wn * WN + ni * 8 + lc * 2;
            float bv0 = 0.f, bv1 = 0.f;
            if (BIAS) { bv0 = bias[n]; bv1 = bias[n + 1]; }
#pragma unroll
            for (int half = 0; half < 2; half++) {
                int m = bm + wm * WM + mi * 16 + lr + half * 8;
                *(float2*)&C[(size_t)m * BN + n] =
                    make_float2(acc[mi][ni][half * 2 + 0] + bv0,
                                acc[mi][ni][half * 2 + 1] + bv1);
            }
        }
}

// ---------------- pooling (gather -> fp16 segmax) ----------------
__global__ void k_poolmax4() {
    int t = blockIdx.x * 256 + threadIdx.x;   // 3*NSEG*32
    int f4 = t & 31;
    int bin = (t >> 5) & (NSEG - 1);
    int pl = t >> 21;
    int cnt = g_bcnt[pl][bin];
    if (cnt == 0) return;
    int off = g_boff[pl][bin] + g_bsum[pl][bin >> 11];
    float4 m = make_float4(-FLT_MAX, -FLT_MAX, -FLT_MAX, -FLT_MAX);
    for (int j = 0; j < cnt; j++) {
        int pt = g_pts[pl][off + j];
        float4 v = *(const float4*)&g_net[(size_t)pt * H + f4 * 4];
        m.x = fmaxf(m.x, v.x); m.y = fmaxf(m.y, v.y);
        m.z = fmaxf(m.z, v.z); m.w = fmaxf(m.w, v.w);
    }
    __half2* dst = (__half2*)&g_segmax[pl][(size_t)bin * H + f4 * 4];
    dst[0] = __floats2half2_rn(m.x, m.y);
    dst[1] = __floats2half2_rn(m.z, m.w);
}

// ---------------- fused mean + transposed output ----------------
// out layout: [plane][b][ch][pix]
__global__ void __launch_bounds__(256)
k_meanout(float* __restrict__ out) {
    __shared__ float smean[32][72];       // 72 floats = 288 B row: float4-aligned
    int pix0 = blockIdx.x * 32;
    int pb = blockIdx.y;                  // pl*4 + b
    int pl = pb >> 2, b = pb & 3;
    int t = threadIdx.x;

    int binl = t >> 3;                    // 32 bins, 8 threads each
    int c8 = (t & 7) * 8;                 // 8 channels per thread
    int bin = b * R2_ + pix0 + binl;
    int cnt = g_bcnt[pl][bin];
    float4 s0 = make_float4(0.f, 0.f, 0.f, 0.f);
    float4 s1 = make_float4(0.f, 0.f, 0.f, 0.f);
    if (cnt > 0) {
        int off = g_boff[pl][bin] + g_bsum[pl][bin >> 11];
        for (int j = 0; j < cnt; j++) {
            int pt = g_pts[pl][off + j];
            float4 v0 = *(const float4*)&g_c[(size_t)pt * CDIM + c8];
            float4 v1 = *(const float4*)&g_c[(size_t)pt * CDIM + c8 + 4];
            s0.x += v0.x; s0.y += v0.y; s0.z += v0.z; s0.w += v0.w;
            s1.x += v1.x; s1.y += v1.y; s1.z += v1.z; s1.w += v1.w;
        }
        float inv = 1.0f / (float)cnt;
        s0.x *= inv; s0.y *= inv; s0.z *= inv; s0.w *= inv;
        s1.x *= inv; s1.y *= inv; s1.z *= inv; s1.w *= inv;
    }
    *(float4*)&smean[binl][c8] = s0;
    *(float4*)&smean[binl][c8 + 4] = s1;
    __syncthreads();

    int tx = t & 31;          // pix
    int ty = t >> 5;          // 8 ch-groups
#pragma unroll
    for (int k = 0; k < 8; k++) {
        int ch = ty * 8 + k;
        out[((size_t)pb * CDIM + ch) * R2_ + pix0 + tx] = smean[tx][ch];
    }
}

// ---------------- launcher ----------------
extern "C" void kernel_launch(void* const* d_in, const int* in_sizes, int n_in,
                              void* d_out, int out_size) {
    const float* p   = (const float*)d_in[0];
    const float* fw  = (const float*)d_in[1];
    const float* fb  = (const float*)d_in[2];
    const float* w0  = (const float*)d_in[3];
    const float* b0  = (const float*)d_in[4];
    const float* w1  = (const float*)d_in[5];
    const float* b1  = (const float*)d_in[6];
    const float* ws  = (const float*)d_in[7];
    const float* fcw = (const float*)d_in[8];
    const float* fcb = (const float*)d_in[9];
    float* out = (float*)d_out;

    float *gn, *gc;
    cudaGetSymbolAddress((void**)&gn, g_net);
    cudaGetSymbolAddress((void**)&gc, g_c);

    static bool attr_done = false;
    if (!attr_done) {
        cudaFuncSetAttribute(k_resblock<0>,
                             cudaFuncAttributeMaxDynamicSharedMemorySize, RB_SMEM_BYTES);
        cudaFuncSetAttribute(k_resblock<1>,
                             cudaFuncAttributeMaxDynamicSharedMemorySize, RB_SMEM_BYTES);
        attr_done = true;
    }

    // CSR build, with rb<0> interleaved (independent of scan) so that the
    // profiler's capture window (4th launch) lands on the resblock.
    k_zerobcnt<<<(3 * NSEG) / 256, 256>>>();
    k_idxcount<<<BT / 256, 256>>>(p);
    k_scanA<<<dim3(32, 3), 1024>>>();
    k_resblock<0><<<BT / 128, 256, RB_SMEM_BYTES>>>(
        p, fw, fb, w0, b0, w1, b1, ws, gn);                      // 4th launch
    k_scanB<<<1, 96>>>();
    k_scatter<<<BT / 256, 256>>>();

    for (int i = 1; i < NB; i++) {
        k_poolmax4<<<(3 * NSEG * 32) / 256, 256>>>();
        k_resblock<1><<<BT / 128, 256, RB_SMEM_BYTES>>>(
            nullptr, nullptr, nullptr,
            w0 + (size_t)i * H2 * H, b0 + (size_t)i * H,
            w1 + (size_t)i * H * H, b1 + (size_t)i * H,
            ws + (size_t)i * H2 * H, gn);
    }

    // c = net @ fc_c_w + fc_c_b
    k_mma<64, true, 4, 2><<<BT / 128, 256>>>(gn, fcw, fcb, gc, BT, H);

    k_meanout<<<dim3(R2_ / 32, 3 * B_), 256>>>(out);
}

// round 7
// speedup vs baseline: 2.9852x; 1.0152x over previous
#include <cuda_runtime.h>
#include <cuda_fp16.h>
#include <float.h>
#include <math.h>

// ---------------- problem constants ----------------
#define B_    4
#define T_    32768
#define BT    (B_ * T_)          // 131072 points
#define RESO_ 128
#define R2_   (RESO_ * RESO_)    // 16384
#define NSEG  (B_ * R2_)         // 65536 segments
#define H     128
#define H2    256
#define CDIM  64
#define NB    5

// ---------------- scratch (device globals, no allocation) ----------------
__device__ int    g_idx[3][BT];
__device__ int    g_rank[3][BT];
__device__ int    g_bcnt[3][NSEG];
__device__ int    g_boff[3][NSEG];        // chunk-local exclusive offsets
__device__ int    g_bsum[3][32];          // exclusive chunk base offsets
__device__ int    g_pts[3][BT];
__device__ float  g_net[(size_t)BT * H];
__device__ __align__(16) __half g_segmax[3][(size_t)NSEG * H];
__device__ float  g_c[(size_t)BT * CDIM];

// ---------------- helpers ----------------
__device__ __forceinline__ int norm_bin(float v) {
    float u = v / 1.10001f + 0.5f;
    u = fminf(fmaxf(u, 0.0f), 0.99999f);
    int q = (int)(u * 128.0f);
    return q < 127 ? q : 127;
}

__device__ __forceinline__ unsigned f2tf32(float f) {
    unsigned u;
    asm("cvt.rna.tf32.f32 %0, %1;" : "=r"(u) : "f"(f));
    return u;
}

// ---------------- index / CSR build ----------------
__global__ void k_zerobcnt() {
    int t = blockIdx.x * 256 + threadIdx.x;   // 3*NSEG
    (&g_bcnt[0][0])[t] = 0;
}

__global__ void k_idxcount(const float* __restrict__ p) {
    int i = blockIdx.x * 256 + threadIdx.x;
    if (i >= BT) return;
    float x = p[3 * i + 0], y = p[3 * i + 1], z = p[3 * i + 2];
    int base = (i / T_) * R2_;
    int ix = norm_bin(x), iy = norm_bin(y), iz = norm_bin(z);
    int idx0 = base + ix + RESO_ * iz;
    int idx1 = base + ix + RESO_ * iy;
    int idx2 = base + iy + RESO_ * iz;
    g_idx[0][i] = idx0; g_idx[1][i] = idx1; g_idx[2][i] = idx2;
    g_rank[0][i] = atomicAdd(&g_bcnt[0][idx0], 1);
    g_rank[1][i] = atomicAdd(&g_bcnt[1][idx1], 1);
    g_rank[2][i] = atomicAdd(&g_bcnt[2][idx2], 1);
}

__global__ void k_scanA() {       // 2048-elem chunks, 32 chunks/plane
    int pl = blockIdx.y, chunk = blockIdx.x;
    int tid = threadIdx.x;
    int base = chunk * 2048 + tid * 2;
    int v0 = g_bcnt[pl][base], v1 = g_bcnt[pl][base + 1];
    int v = v0 + v1;
    int lane = tid & 31, wid = tid >> 5;
    int x = v;
#pragma unroll
    for (int o = 1; o < 32; o <<= 1) {
        int y = __shfl_up_sync(0xffffffffu, x, o);
        if (lane >= o) x += y;
    }
    __shared__ int wsum[32];
    if (lane == 31) wsum[wid] = x;
    __syncthreads();
    if (wid == 0) {
        int s = wsum[lane];
#pragma unroll
        for (int o = 1; o < 32; o <<= 1) {
            int y = __shfl_up_sync(0xffffffffu, s, o);
            if (lane >= o) s += y;
        }
        wsum[lane] = s;
    }
    __syncthreads();
    int incl = x + (wid ? wsum[wid - 1] : 0);
    int excl = incl - v;
    g_boff[pl][base] = excl;
    g_boff[pl][base + 1] = excl + v0;
    if (tid == 1023) g_bsum[pl][chunk] = incl;
}

__global__ void k_scanB() {       // 1 block, 96 threads: warp per plane
    int pl = threadIdx.x >> 5, lane = threadIdx.x & 31;
    int v = g_bsum[pl][lane];
    int x = v;
#pragma unroll
    for (int o = 1; o < 32; o <<= 1) {
        int y = __shfl_up_sync(0xffffffffu, x, o);
        if (lane >= o) x += y;
    }
    g_bsum[pl][lane] = x - v;     // exclusive chunk base
}

__global__ void k_scatter() {
    int i = blockIdx.x * 256 + threadIdx.x;   // BT
#pragma unroll
    for (int pl = 0; pl < 3; pl++) {
        int bin = g_idx[pl][i];
        int off = g_boff[pl][bin] + g_bsum[pl][bin >> 11];
        g_pts[pl][off + g_rank[pl][i]] = i;
    }
}

// ---------------- fused resblock kernel (BM=128, 512 threads) ----------------
// MODE 0: X = fc_pos(p) inline.  MODE 1: X = [net | sum3 segmax(idx)] inline.
// NET[tile,128] = X@ws + relu(relu(X)@w0 + b0)@w1 + b1
// 16 warps (wm 4 x wn 4), warp tile 32x32, TM=2, TN=4.
#define RB_SR 136      // stride mod 32 == 8 -> conflict-free fragment loads
#define RB_AS(buf, k, m)  sm[(buf) * (16 * RB_SR) + (k) * RB_SR + (m)]
#define RB_B0(buf, k, n)  sm[4352 + (buf) * (16 * RB_SR) + (k) * RB_SR + (n)]
#define RB_BS(buf, k, n)  sm[8704 + (buf) * (16 * RB_SR) + (k) * RB_SR + (n)]
#define RB_HS(k, m)       sm[13056 + (k) * RB_SR + (m)]
#define RB_SMEM_BYTES ((13056 + 128 * RB_SR) * 4)   // 121856 B

template <int MODE>
__global__ void __launch_bounds__(512, 1)
k_resblock(const float* __restrict__ P,    // MODE 0: [BT,3]
           const float* __restrict__ FW,   // MODE 0: [3,256]
           const float* __restrict__ FB,   // MODE 0: [256]
           const float* __restrict__ w0,   // [256,128]
           const float* __restrict__ b0,   // [128]
           const float* __restrict__ w1,   // [128,128]
           const float* __restrict__ b1,   // [128]
           const float* __restrict__ ws,   // [256,128]
           float* __restrict__ NET) {      // [BT,128] (in-place safe)
    extern __shared__ unsigned sm[];
    int tid = threadIdx.x;
    int bm = blockIdx.x * 128;
    int w = tid >> 5, lane = tid & 31;
    int wm = w & 3, wn = w >> 2;              // 4 x 4
    int lr = lane >> 2, lc = lane & 3;

    int arow = tid >> 2;            // 0..127, one row per thread
    int acol = (tid & 3) * 4;
    int brow = tid >> 5;            // 0..15
    int bcol = (tid & 31) * 4;      // 0..124

    // per-row state for A synthesis (1 row per thread)
    float pr[3];
    int ixr[3];
    {
        int row = bm + arow;
        if (MODE == 0) {
            pr[0] = P[3 * row]; pr[1] = P[3 * row + 1]; pr[2] = P[3 * row + 2];
        } else {
            ixr[0] = g_idx[0][row]; ixr[1] = g_idx[1][row]; ixr[2] = g_idx[2][row];
        }
    }

    float accH[2][4][4];
    float accS[2][4][4];
#pragma unroll
    for (int mi = 0; mi < 2; mi++)
#pragma unroll
        for (int ni = 0; ni < 4; ni++)
#pragma unroll
            for (int q = 0; q < 4; q++) { accH[mi][ni][q] = 0.f; accS[mi][ni][q] = 0.f; }

    float4 ar, b0r, bsr;

    auto loadA = [&](int k0) -> float4 {
        int col = k0 + acol;
        if (MODE == 0) {
            float4 wa = *(const float4*)&FW[col];
            float4 wb = *(const float4*)&FW[H2 + col];
            float4 wc = *(const float4*)&FW[2 * H2 + col];
            float4 bb = *(const float4*)&FB[col];
            return make_float4(pr[0] * wa.x + pr[1] * wb.x + pr[2] * wc.x + bb.x,
                               pr[0] * wa.y + pr[1] * wb.y + pr[2] * wc.y + bb.y,
                               pr[0] * wa.z + pr[1] * wb.z + pr[2] * wc.z + bb.z,
                               pr[0] * wa.w + pr[1] * wb.w + pr[2] * wc.w + bb.w);
        } else {
            if (col < H) {   // uniform per k-tile
                return *(const float4*)&NET[(size_t)(bm + arow) * H + col];
            } else {
                int c2 = col - H;
                uint2 ua = *(const uint2*)&g_segmax[0][(size_t)ixr[0] * H + c2];
                uint2 ub = *(const uint2*)&g_segmax[1][(size_t)ixr[1] * H + c2];
                uint2 uc = *(const uint2*)&g_segmax[2][(size_t)ixr[2] * H + c2];
                float2 a0 = __half22float2(*(__half2*)&ua.x), a1 = __half22float2(*(__half2*)&ua.y);
                float2 e0 = __half22float2(*(__half2*)&ub.x), e1 = __half22float2(*(__half2*)&ub.y);
                float2 c0 = __half22float2(*(__half2*)&uc.x), c1 = __half22float2(*(__half2*)&uc.y);
                return make_float4(a0.x + e0.x + c0.x, a0.y + e0.y + c0.y,
                                   a1.x + e1.x + c1.x, a1.y + e1.y + c1.y);
            }
        }
    };

    // ---- phase 1: K=256, accH = relu(X)@w0, accS = X@ws ----
    ar = loadA(0);
    b0r = *(const float4*)&w0[(size_t)brow * H + bcol];
    bsr = *(const float4*)&ws[(size_t)brow * H + bcol];
    RB_AS(0, acol + 0, arow) = f2tf32(ar.x);
    RB_AS(0, acol + 1, arow) = f2tf32(ar.y);
    RB_AS(0, acol + 2, arow) = f2tf32(ar.z);
    RB_AS(0, acol + 3, arow) = f2tf32(ar.w);
    RB_B0(0, brow, bcol + 0) = f2tf32(b0r.x);
    RB_B0(0, brow, bcol + 1) = f2tf32(b0r.y);
    RB_B0(0, brow, bcol + 2) = f2tf32(b0r.z);
    RB_B0(0, brow, bcol + 3) = f2tf32(b0r.w);
    RB_BS(0, brow, bcol + 0) = f2tf32(bsr.x);
    RB_BS(0, brow, bcol + 1) = f2tf32(bsr.y);
    RB_BS(0, brow, bcol + 2) = f2tf32(bsr.z);
    RB_BS(0, brow, bcol + 3) = f2tf32(bsr.w);
    __syncthreads();

    for (int kt = 0; kt < 16; kt++) {
        int cur = kt & 1;
        if (kt + 1 < 16) {
            int k0 = (kt + 1) * 16;
            ar = loadA(k0);
            b0r = *(const float4*)&w0[(size_t)(k0 + brow) * H + bcol];
            bsr = *(const float4*)&ws[(size_t)(k0 + brow) * H + bcol];
        }
#pragma unroll
        for (int ks = 0; ks < 2; ks++) {
            unsigned afr[2][4], afh[2][4], bf0[4][2], bfs[4][2];
#pragma unroll
            for (int mi = 0; mi < 2; mi++) {
                int m = wm * 32 + mi * 16 + lr;
                int k = ks * 8 + lc;
                afr[mi][0] = RB_AS(cur, k, m);
                afr[mi][1] = RB_AS(cur, k, m + 8);
                afr[mi][2] = RB_AS(cur, k + 4, m);
                afr[mi][3] = RB_AS(cur, k + 4, m + 8);
#pragma unroll
                for (int q = 0; q < 4; q++)
                    afh[mi][q] = __float_as_uint(fmaxf(__uint_as_float(afr[mi][q]), 0.f));
            }
#pragma unroll
            for (int ni = 0; ni < 4; ni++) {
                int n = wn * 32 + ni * 8 + lr;
                bf0[ni][0] = RB_B0(cur, ks * 8 + lc, n);
                bf0[ni][1] = RB_B0(cur, ks * 8 + 4 + lc, n);
                bfs[ni][0] = RB_BS(cur, ks * 8 + lc, n);
                bfs[ni][1] = RB_BS(cur, ks * 8 + 4 + lc, n);
            }
#pragma unroll
            for (int mi = 0; mi < 2; mi++)
#pragma unroll
                for (int ni = 0; ni < 4; ni++) {
                    asm volatile(
                        "mma.sync.aligned.m16n8k8.row.col.f32.tf32.tf32.f32 "
                        "{%0,%1,%2,%3}, {%4,%5,%6,%7}, {%8,%9}, {%0,%1,%2,%3};"
                        : "+f"(accH[mi][ni][0]), "+f"(accH[mi][ni][1]),
                          "+f"(accH[mi][ni][2]), "+f"(accH[mi][ni][3])
                        : "r"(afh[mi][0]), "r"(afh[mi][1]), "r"(afh[mi][2]), "r"(afh[mi][3]),
                          "r"(bf0[ni][0]), "r"(bf0[ni][1]));
                    asm volatile(
                        "mma.sync.aligned.m16n8k8.row.col.f32.tf32.tf32.f32 "
                        "{%0,%1,%2,%3}, {%4,%5,%6,%7}, {%8,%9}, {%0,%1,%2,%3};"
                        : "+f"(accS[mi][ni][0]), "+f"(accS[mi][ni][1]),
                          "+f"(accS[mi][ni][2]), "+f"(accS[mi][ni][3])
                        : "r"(afr[mi][0]), "r"(afr[mi][1]), "r"(afr[mi][2]), "r"(afr[mi][3]),
                          "r"(bfs[ni][0]), "r"(bfs[ni][1]));
                }
        }
        if (kt + 1 < 16) {
            int nxt = cur ^ 1;
            RB_AS(nxt, acol + 0, arow) = f2tf32(ar.x);
            RB_AS(nxt, acol + 1, arow) = f2tf32(ar.y);
            RB_AS(nxt, acol + 2, arow) = f2tf32(ar.z);
            RB_AS(nxt, acol + 3, arow) = f2tf32(ar.w);
            RB_B0(nxt, brow, bcol + 0) = f2tf32(b0r.x);
            RB_B0(nxt, brow, bcol + 1) = f2tf32(b0r.y);
            RB_B0(nxt, brow, bcol + 2) = f2tf32(b0r.z);
            RB_B0(nxt, brow, bcol + 3) = f2tf32(b0r.w);
            RB_BS(nxt, brow, bcol + 0) = f2tf32(bsr.x);
            RB_BS(nxt, brow, bcol + 1) = f2tf32(bsr.y);
            RB_BS(nxt, brow, bcol + 2) = f2tf32(bsr.z);
            RB_BS(nxt, brow, bcol + 3) = f2tf32(bsr.w);
        }
        __syncthreads();
    }

    // ---- store Hs = relu(accH + b0) (layout [n][m], tf32) ----
#pragma unroll
    for (int mi = 0; mi < 2; mi++)
#pragma unroll
        for (int ni = 0; ni < 4; ni++) {
            int n = wn * 32 + ni * 8 + lc * 2;
            float bv0 = b0[n], bv1 = b0[n + 1];
#pragma unroll
            for (int half = 0; half < 2; half++) {
                int m = wm * 32 + mi * 16 + lr + half * 8;
                RB_HS(n, m)     = f2tf32(fmaxf(accH[mi][ni][half * 2 + 0] + bv0, 0.f));
                RB_HS(n + 1, m) = f2tf32(fmaxf(accH[mi][ni][half * 2 + 1] + bv1, 0.f));
            }
        }
    b0r = *(const float4*)&w1[(size_t)brow * H + bcol];
    __syncthreads();   // Hs visible; phase-1 B0s dead
    RB_B0(0, brow, bcol + 0) = f2tf32(b0r.x);
    RB_B0(0, brow, bcol + 1) = f2tf32(b0r.y);
    RB_B0(0, brow, bcol + 2) = f2tf32(b0r.z);
    RB_B0(0, brow, bcol + 3) = f2tf32(b0r.w);
    __syncthreads();

    // ---- phase 2: accS += Hs @ w1, K=128 ----
    for (int kt = 0; kt < 8; kt++) {
        int cur = kt & 1;
        if (kt + 1 < 8) {
            int k0 = (kt + 1) * 16;
            b0r = *(const float4*)&w1[(size_t)(k0 + brow) * H + bcol];
        }
#pragma unroll
        for (int ks = 0; ks < 2; ks++) {
            unsigned af[2][4], bf[4][2];
            int kk = kt * 16 + ks * 8 + lc;
#pragma unroll
            for (int mi = 0; mi < 2; mi++) {
                int m = wm * 32 + mi * 16 + lr;
                af[mi][0] = RB_HS(kk, m);
                af[mi][1] = RB_HS(kk, m + 8);
                af[mi][2] = RB_HS(kk + 4, m);
                af[mi][3] = RB_HS(kk + 4, m + 8);
            }
#pragma unroll
            for (int ni = 0; ni < 4; ni++) {
                int n = wn * 32 + ni * 8 + lr;
                bf[ni][0] = RB_B0(cur, ks * 8 + lc, n);
                bf[ni][1] = RB_B0(cur, ks * 8 + 4 + lc, n);
            }
#pragma unroll
            for (int mi = 0; mi < 2; mi++)
#pragma unroll
                for (int ni = 0; ni < 4; ni++) {
                    asm volatile(
                        "mma.sync.aligned.m16n8k8.row.col.f32.tf32.tf32.f32 "
                        "{%0,%1,%2,%3}, {%4,%5,%6,%7}, {%8,%9}, {%0,%1,%2,%3};"
                        : "+f"(accS[mi][ni][0]), "+f"(accS[mi][ni][1]),
                          "+f"(accS[mi][ni][2]), "+f"(accS[mi][ni][3])
                        : "r"(af[mi][0]), "r"(af[mi][1]), "r"(af[mi][2]), "r"(af[mi][3]),
                          "r"(bf[ni][0]), "r"(bf[ni][1]));
                }
        }
        if (kt + 1 < 8) {
            int nxt = cur ^ 1;
            RB_B0(nxt, brow, bcol + 0) = f2tf32(b0r.x);
            RB_B0(nxt, brow, bcol + 1) = f2tf32(b0r.y);
            RB_B0(nxt, brow, bcol + 2) = f2tf32(b0r.z);
            RB_B0(nxt, brow, bcol + 3) = f2tf32(b0r.w);
        }
        __syncthreads();
    }

    // ---- epilogue: NET = accS + b1 ----
#pragma unroll
    for (int mi = 0; mi < 2; mi++)
#pragma unroll
        for (int ni = 0; ni < 4; ni++) {
            int n = wn * 32 + ni * 8 + lc * 2;
            float bv0 = b1[n], bv1 = b1[n + 1];
#pragma unroll
            for (int half = 0; half < 2; half++) {
                int m = bm + wm * 32 + mi * 16 + lr + half * 8;
                *(float2*)&NET[(size_t)m * H + n] =
                    make_float2(accS[mi][ni][half * 2 + 0] + bv0,
                                accS[mi][ni][half * 2 + 1] + bv1);
            }
        }
}

// ---------------- generic TF32 GEMM (fc_c) ----------------
template <int BN, bool BIAS, int WARPS_M, int WARPS_N>
__global__ void __launch_bounds__(256)
k_mma(const float* __restrict__ A, const float* __restrict__ W,
      const float* __restrict__ bias, float* __restrict__ C,
      int M, int K) {
    constexpr int BM = 128, BK = 16;
    constexpr int WM = BM / WARPS_M, WN = BN / WARPS_N;
    constexpr int TM = WM / 16, TN = WN / 8;
    constexpr int ASr = BM + 8, BSr = BN + 8;
    __shared__ unsigned As[2][BK][ASr];
    __shared__ unsigned Bs[2][BK][BSr];
    int tid = threadIdx.x;
    int bm = blockIdx.x * BM;
    int w = tid >> 5, lane = tid & 31;
    int wm = w % WARPS_M, wn = w / WARPS_M;
    int lr = lane >> 2, lc = lane & 3;

    float acc[TM][TN][4];
#pragma unroll
    for (int mi = 0; mi < TM; mi++)
#pragma unroll
        for (int ni = 0; ni < TN; ni++)
#pragma unroll
            for (int q = 0; q < 4; q++) acc[mi][ni][q] = 0.0f;

    int arow = tid >> 2;
    int acol = (tid & 3) * 4;
    int brow = tid >> 4;
    int bcol = (tid & 15) * 4;

    float4 ar[2];
    float4 br;

    {
#pragma unroll
        for (int hh = 0; hh < 2; hh++)
            ar[hh] = *(const float4*)&A[(size_t)(bm + arow + hh * 64) * K + acol];
        br = *(const float4*)&W[(size_t)brow * BN + bcol];
#pragma unroll
        for (int hh = 0; hh < 2; hh++) {
            int row = arow + hh * 64;
            As[0][acol + 0][row] = f2tf32(ar[hh].x);
            As[0][acol + 1][row] = f2tf32(ar[hh].y);
            As[0][acol + 2][row] = f2tf32(ar[hh].z);
            As[0][acol + 3][row] = f2tf32(ar[hh].w);
        }
        Bs[0][brow][bcol + 0] = f2tf32(br.x);
        Bs[0][brow][bcol + 1] = f2tf32(br.y);
        Bs[0][brow][bcol + 2] = f2tf32(br.z);
        Bs[0][brow][bcol + 3] = f2tf32(br.w);
    }
    __syncthreads();

    int KT = K / BK;
    for (int kt = 0; kt < KT; kt++) {
        int cur = kt & 1;
        if (kt + 1 < KT) {
            int k0 = (kt + 1) * BK;
#pragma unroll
            for (int hh = 0; hh < 2; hh++)
                ar[hh] = *(const float4*)&A[(size_t)(bm + arow + hh * 64) * K + k0 + acol];
            br = *(const float4*)&W[(size_t)(k0 + brow) * BN + bcol];
        }
#pragma unroll
        for (int ks = 0; ks < 2; ks++) {
            unsigned af[TM][4], bf[TN][2];
#pragma unroll
            for (int mi = 0; mi < TM; mi++) {
                int m = wm * WM + mi * 16 + lr;
                int k = ks * 8 + lc;
                af[mi][0] = As[cur][k][m];
                af[mi][1] = As[cur][k][m + 8];
                af[mi][2] = As[cur][k + 4][m];
                af[mi][3] = As[cur][k + 4][m + 8];
            }
#pragma unroll
            for (int ni = 0; ni < TN; ni++) {
                int n = wn * WN + ni * 8 + lr;
                bf[ni][0] = Bs[cur][ks * 8 + lc][n];
                bf[ni][1] = Bs[cur][ks * 8 + 4 + lc][n];
            }
#pragma unroll
            for (int mi = 0; mi < TM; mi++)
#pragma unroll
                for (int ni = 0; ni < TN; ni++) {
                    asm volatile(
                        "mma.sync.aligned.m16n8k8.row.col.f32.tf32.tf32.f32 "
                        "{%0,%1,%2,%3}, {%4,%5,%6,%7}, {%8,%9}, {%0,%1,%2,%3};"
                        : "+f"(acc[mi][ni][0]), "+f"(acc[mi][ni][1]),
                          "+f"(acc[mi][ni][2]), "+f"(acc[mi][ni][3])
                        : "r"(af[mi][0]), "r"(af[mi][1]), "r"(af[mi][2]), "r"(af[mi][3]),
                          "r"(bf[ni][0]), "r"(bf[ni][1]));
                }
        }
        if (kt + 1 < KT) {
            int nxt = cur ^ 1;
#pragma unroll
            for (int hh = 0; hh < 2; hh++) {
                int row = arow + hh * 64;
                As[nxt][acol + 0][row] = f2tf32(ar[hh].x);
                As[nxt][acol + 1][row] = f2tf32(ar[hh].y);
                As[nxt][acol + 2][row] = f2tf32(ar[hh].z);
                As[nxt][acol + 3][row] = f2tf32(ar[hh].w);
            }
            Bs[nxt][brow][bcol + 0] = f2tf32(br.x);
            Bs[nxt][brow][bcol + 1] = f2tf32(br.y);
            Bs[nxt][brow][bcol + 2] = f2tf32(br.z);
            Bs[nxt][brow][bcol + 3] = f2tf32(br.w);
        }
        __syncthreads();
    }

#pragma unroll
    for (int mi = 0; mi < TM; mi++)
#pragma unroll
        for (int ni = 0; ni < TN; ni++) {
            int n = wn * WN + ni * 8 + lc * 2;
            float bv0 = 0.f, bv1 = 0.f;
            if (BIAS) { bv0 = bias[n]; bv1 = bias[n + 1]; }
#pragma unroll
            for (int half = 0; half < 2; half++) {
                int m = bm + wm * WM + mi * 16 + lr + half * 8;
                *(float2*)&C[(size_t)m * BN + n] =
                    make_float2(acc[mi][ni][half * 2 + 0] + bv0,
                                acc[mi][ni][half * 2 + 1] + bv1);
            }
        }
}

// ---------------- pooling (gather -> fp16 segmax) ----------------
__global__ void k_poolmax4() {
    int t = blockIdx.x * 256 + threadIdx.x;   // 3*NSEG*32
    int f4 = t & 31;
    int bin = (t >> 5) & (NSEG - 1);
    int pl = t >> 21;
    int cnt = g_bcnt[pl][bin];
    if (cnt == 0) return;
    int off = g_boff[pl][bin] + g_bsum[pl][bin >> 11];
    float4 m = make_float4(-FLT_MAX, -FLT_MAX, -FLT_MAX, -FLT_MAX);
    for (int j = 0; j < cnt; j++) {
        int pt = g_pts[pl][off + j];
        float4 v = *(const float4*)&g_net[(size_t)pt * H + f4 * 4];
        m.x = fmaxf(m.x, v.x); m.y = fmaxf(m.y, v.y);
        m.z = fmaxf(m.z, v.z); m.w = fmaxf(m.w, v.w);
    }
    __half2* dst = (__half2*)&g_segmax[pl][(size_t)bin * H + f4 * 4];
    dst[0] = __floats2half2_rn(m.x, m.y);
    dst[1] = __floats2half2_rn(m.z, m.w);
}

// ---------------- fused mean + transposed output ----------------
// out layout: [plane][b][ch][pix]
__global__ void __launch_bounds__(256)
k_meanout(float* __restrict__ out) {
    __shared__ float smean[32][72];       // 288 B rows: float4-aligned
    int pix0 = blockIdx.x * 32;
    int pb = blockIdx.y;                  // pl*4 + b
    int pl = pb >> 2, b = pb & 3;
    int t = threadIdx.x;

    int binl = t >> 3;                    // 32 bins, 8 threads each
    int c8 = (t & 7) * 8;                 // 8 channels per thread
    int bin = b * R2_ + pix0 + binl;
    int cnt = g_bcnt[pl][bin];
    float4 s0 = make_float4(0.f, 0.f, 0.f, 0.f);
    float4 s1 = make_float4(0.f, 0.f, 0.f, 0.f);
    if (cnt > 0) {
        int off = g_boff[pl][bin] + g_bsum[pl][bin >> 11];
        for (int j = 0; j < cnt; j++) {
            int pt = g_pts[pl][off + j];
            float4 v0 = *(const float4*)&g_c[(size_t)pt * CDIM + c8];
            float4 v1 = *(const float4*)&g_c[(size_t)pt * CDIM + c8 + 4];
            s0.x += v0.x; s0.y += v0.y; s0.z += v0.z; s0.w += v0.w;
            s1.x += v1.x; s1.y += v1.y; s1.z += v1.z; s1.w += v1.w;
        }
        float inv = 1.0f / (float)cnt;
        s0.x *= inv; s0.y *= inv; s0.z *= inv; s0.w *= inv;
        s1.x *= inv; s1.y *= inv; s1.z *= inv; s1.w *= inv;
    }
    *(float4*)&smean[binl][c8] = s0;
    *(float4*)&smean[binl][c8 + 4] = s1;
    __syncthreads();

    int tx = t & 31;          // pix
    int ty = t >> 5;          // 8 ch-groups
#pragma unroll
    for (int k = 0; k < 8; k++) {
        int ch = ty * 8 + k;
        out[((size_t)pb * CDIM + ch) * R2_ + pix0 + tx] = smean[tx][ch];
    }
}

// ---------------- launcher ----------------
extern "C" void kernel_launch(void* const* d_in, const int* in_sizes, int n_in,
                              void* d_out, int out_size) {
    const float* p   = (const float*)d_in[0];
    const float* fw  = (const float*)d_in[1];
    const float* fb  = (const float*)d_in[2];
    const float* w0  = (const float*)d_in[3];
    const float* b0  = (const float*)d_in[4];
    const float* w1  = (const float*)d_in[5];
    const float* b1  = (const float*)d_in[6];
    const float* ws  = (const float*)d_in[7];
    const float* fcw = (const float*)d_in[8];
    const float* fcb = (const float*)d_in[9];
    float* out = (float*)d_out;

    float *gn, *gc;
    cudaGetSymbolAddress((void**)&gn, g_net);
    cudaGetSymbolAddress((void**)&gc, g_c);

    static bool attr_done = false;
    if (!attr_done) {
        cudaFuncSetAttribute(k_resblock<0>,
                             cudaFuncAttributeMaxDynamicSharedMemorySize, RB_SMEM_BYTES);
        cudaFuncSetAttribute(k_resblock<1>,
                             cudaFuncAttributeMaxDynamicSharedMemorySize, RB_SMEM_BYTES);
        attr_done = true;
    }

    // CSR build, with rb<0> interleaved so the profiler's 4th-launch window
    // lands on the resblock.
    k_zerobcnt<<<(3 * NSEG) / 256, 256>>>();
    k_idxcount<<<BT / 256, 256>>>(p);
    k_scanA<<<dim3(32, 3), 1024>>>();
    k_resblock<0><<<BT / 128, 512, RB_SMEM_BYTES>>>(
        p, fw, fb, w0, b0, w1, b1, ws, gn);                      // 4th launch
    k_scanB<<<1, 96>>>();
    k_scatter<<<BT / 256, 256>>>();

    for (int i = 1; i < NB; i++) {
        k_poolmax4<<<(3 * NSEG * 32) / 256, 256>>>();
        k_resblock<1><<<BT / 128, 512, RB_SMEM_BYTES>>>(
            nullptr, nullptr, nullptr,
            w0 + (size_t)i * H2 * H, b0 + (size_t)i * H,
            w1 + (size_t)i * H * H, b1 + (size_t)i * H,
            ws + (size_t)i * H2 * H, gn);
    }

    // c = net @ fc_c_w + fc_c_b
    k_mma<64, true, 4, 2><<<BT / 128, 256>>>(gn, fcw, fcb, gc, BT, H);

    k_meanout<<<dim3(R2_ / 32, 3 * B_), 256>>>(out);
}

// round 8
// speedup vs baseline: 3.4984x; 1.1719x over previous
#include <cuda_runtime.h>
#include <cuda_fp16.h>
#include <float.h>
#include <math.h>

// ---------------- problem constants ----------------
#define B_    4
#define T_    32768
#define BT    (B_ * T_)          // 131072 points
#define RESO_ 128
#define R2_   (RESO_ * RESO_)    // 16384
#define NSEG  (B_ * R2_)         // 65536 segments
#define H     128
#define H2    256
#define CDIM  64
#define NB    5

// ---------------- scratch (device globals, no allocation) ----------------
__device__ int    g_idx[3][BT];
__device__ int    g_rank[3][BT];
__device__ int    g_bcnt[3][NSEG];
__device__ int    g_boff[3][NSEG];        // chunk-local exclusive offsets
__device__ int    g_bsum[3][32];          // exclusive chunk base offsets
__device__ int    g_pts[3][BT];
__device__ __align__(16) __half g_net[(size_t)BT * H];
__device__ __align__(16) __half g_segmax[3][(size_t)NSEG * H];
__device__ float  g_c[(size_t)BT * CDIM];

// ---------------- helpers ----------------
__device__ __forceinline__ int norm_bin(float v) {
    float u = v / 1.10001f + 0.5f;
    u = fminf(fmaxf(u, 0.0f), 0.99999f);
    int q = (int)(u * 128.0f);
    return q < 127 ? q : 127;
}

__device__ __forceinline__ unsigned f2tf32(float f) {
    unsigned u;
    asm("cvt.rna.tf32.f32 %0, %1;" : "=r"(u) : "f"(f));
    return u;
}

// ---------------- index / CSR build ----------------
__global__ void k_zerobcnt() {
    int t = blockIdx.x * 256 + threadIdx.x;   // 3*NSEG
    (&g_bcnt[0][0])[t] = 0;
}

__global__ void k_idxcount(const float* __restrict__ p) {
    int i = blockIdx.x * 256 + threadIdx.x;
    if (i >= BT) return;
    float x = p[3 * i + 0], y = p[3 * i + 1], z = p[3 * i + 2];
    int base = (i / T_) * R2_;
    int ix = norm_bin(x), iy = norm_bin(y), iz = norm_bin(z);
    int idx0 = base + ix + RESO_ * iz;
    int idx1 = base + ix + RESO_ * iy;
    int idx2 = base + iy + RESO_ * iz;
    g_idx[0][i] = idx0; g_idx[1][i] = idx1; g_idx[2][i] = idx2;
    g_rank[0][i] = atomicAdd(&g_bcnt[0][idx0], 1);
    g_rank[1][i] = atomicAdd(&g_bcnt[1][idx1], 1);
    g_rank[2][i] = atomicAdd(&g_bcnt[2][idx2], 1);
}

__global__ void k_scanA() {       // 2048-elem chunks, 32 chunks/plane
    int pl = blockIdx.y, chunk = blockIdx.x;
    int tid = threadIdx.x;
    int base = chunk * 2048 + tid * 2;
    int v0 = g_bcnt[pl][base], v1 = g_bcnt[pl][base + 1];
    int v = v0 + v1;
    int lane = tid & 31, wid = tid >> 5;
    int x = v;
#pragma unroll
    for (int o = 1; o < 32; o <<= 1) {
        int y = __shfl_up_sync(0xffffffffu, x, o);
        if (lane >= o) x += y;
    }
    __shared__ int wsum[32];
    if (lane == 31) wsum[wid] = x;
    __syncthreads();
    if (wid == 0) {
        int s = wsum[lane];
#pragma unroll
        for (int o = 1; o < 32; o <<= 1) {
            int y = __shfl_up_sync(0xffffffffu, s, o);
            if (lane >= o) s += y;
        }
        wsum[lane] = s;
    }
    __syncthreads();
    int incl = x + (wid ? wsum[wid - 1] : 0);
    int excl = incl - v;
    g_boff[pl][base] = excl;
    g_boff[pl][base + 1] = excl + v0;
    if (tid == 1023) g_bsum[pl][chunk] = incl;
}

__global__ void k_scanB() {       // 1 block, 96 threads: warp per plane
    int pl = threadIdx.x >> 5, lane = threadIdx.x & 31;
    int v = g_bsum[pl][lane];
    int x = v;
#pragma unroll
    for (int o = 1; o < 32; o <<= 1) {
        int y = __shfl_up_sync(0xffffffffu, x, o);
        if (lane >= o) x += y;
    }
    g_bsum[pl][lane] = x - v;     // exclusive chunk base
}

__global__ void k_scatter() {
    int i = blockIdx.x * 256 + threadIdx.x;   // BT
#pragma unroll
    for (int pl = 0; pl < 3; pl++) {
        int bin = g_idx[pl][i];
        int off = g_boff[pl][bin] + g_bsum[pl][bin >> 11];
        g_pts[pl][off + g_rank[pl][i]] = i;
    }
}

// ---------------- fused resblock kernel (BM=64, 256 threads, 2 CTAs/SM) ----
// MODE 0: X = fc_pos(p) inline.  MODE 1: X = [net | sum3 segmax(idx)] inline.
// NET[tile,128] = X@ws + relu(relu(X)@w0 + b0)@w1 + b1
// 8 warps (wm 2 x wn 4), warp tile 32x32, TM=2, TN=4.
#define RB_ASR 72      // stride mod 32 == 8 -> conflict-free fragment loads
#define RB_BSR 136
#define RB_AS(buf, k, m)  sm[(buf) * (16 * RB_ASR) + (k) * RB_ASR + (m)]
#define RB_B0(buf, k, n)  sm[2304 + (buf) * (16 * RB_BSR) + (k) * RB_BSR + (n)]
#define RB_BS(buf, k, n)  sm[6656 + (buf) * (16 * RB_BSR) + (k) * RB_BSR + (n)]
#define RB_HS(k, m)       sm[11008 + (k) * RB_ASR + (m)]
#define RB_SMEM_BYTES ((11008 + 128 * RB_ASR) * 4)   // 80896 B

template <int MODE>
__global__ void __launch_bounds__(256, 2)
k_resblock(const float* __restrict__ P,    // MODE 0: [BT,3]
           const float* __restrict__ FW,   // MODE 0: [3,256]
           const float* __restrict__ FB,   // MODE 0: [256]
           const float* __restrict__ w0,   // [256,128]
           const float* __restrict__ b0,   // [128]
           const float* __restrict__ w1,   // [128,128]
           const float* __restrict__ b1,   // [128]
           const float* __restrict__ ws,   // [256,128]
           __half* __restrict__ NET) {     // [BT,128] fp16 (in-place safe)
    extern __shared__ unsigned sm[];
    int tid = threadIdx.x;
    int bm = blockIdx.x * 64;
    int w = tid >> 5, lane = tid & 31;
    int wm = w & 1, wn = w >> 1;              // 2 x 4
    int lr = lane >> 2, lc = lane & 3;

    int arow = tid >> 2;            // 0..63
    int acol = (tid & 3) * 4;       // 0,4,8,12
    int brow = tid >> 4;            // 0..15
    int bcol = (tid & 15) * 4;      // 0..60

    // per-row state for A synthesis
    int row = bm + arow;
    float p0, p1, p2;
    int ix0, ix1, ix2;
    if (MODE == 0) {
        p0 = P[3 * row]; p1 = P[3 * row + 1]; p2 = P[3 * row + 2];
    } else {
        ix0 = g_idx[0][row]; ix1 = g_idx[1][row]; ix2 = g_idx[2][row];
    }

    float accH[2][4][4];
    float accS[2][4][4];
#pragma unroll
    for (int mi = 0; mi < 2; mi++)
#pragma unroll
        for (int ni = 0; ni < 4; ni++)
#pragma unroll
            for (int q = 0; q < 4; q++) { accH[mi][ni][q] = 0.f; accS[mi][ni][q] = 0.f; }

    float4 ar, b0r[2], bsr[2];

    auto loadA = [&](int k0) -> float4 {
        int col = k0 + acol;
        if (MODE == 0) {
            float4 wa = *(const float4*)&FW[col];
            float4 wb = *(const float4*)&FW[H2 + col];
            float4 wc = *(const float4*)&FW[2 * H2 + col];
            float4 bb = *(const float4*)&FB[col];
            return make_float4(p0 * wa.x + p1 * wb.x + p2 * wc.x + bb.x,
                               p0 * wa.y + p1 * wb.y + p2 * wc.y + bb.y,
                               p0 * wa.z + p1 * wb.z + p2 * wc.z + bb.z,
                               p0 * wa.w + p1 * wb.w + p2 * wc.w + bb.w);
        } else {
            if (col < H) {   // uniform per k-tile: fp16 net
                uint2 un = *(const uint2*)&g_net[(size_t)row * H + col];
                float2 n0 = __half22float2(*(__half2*)&un.x);
                float2 n1 = __half22float2(*(__half2*)&un.y);
                return make_float4(n0.x, n0.y, n1.x, n1.y);
            } else {
                int c2 = col - H;
                uint2 ua = *(const uint2*)&g_segmax[0][(size_t)ix0 * H + c2];
                uint2 ub = *(const uint2*)&g_segmax[1][(size_t)ix1 * H + c2];
                uint2 uc = *(const uint2*)&g_segmax[2][(size_t)ix2 * H + c2];
                float2 a0 = __half22float2(*(__half2*)&ua.x), a1 = __half22float2(*(__half2*)&ua.y);
                float2 e0 = __half22float2(*(__half2*)&ub.x), e1 = __half22float2(*(__half2*)&ub.y);
                float2 c0 = __half22float2(*(__half2*)&uc.x), c1 = __half22float2(*(__half2*)&uc.y);
                return make_float4(a0.x + e0.x + c0.x, a0.y + e0.y + c0.y,
                                   a1.x + e1.x + c1.x, a1.y + e1.y + c1.y);
            }
        }
    };

    // ---- phase 1: K=256, accH = relu(X)@w0, accS = X@ws ----
    ar = loadA(0);
#pragma unroll
    for (int nv = 0; nv < 2; nv++) {
        b0r[nv] = *(const float4*)&w0[(size_t)brow * H + bcol + nv * 64];
        bsr[nv] = *(const float4*)&ws[(size_t)brow * H + bcol + nv * 64];
    }
    RB_AS(0, acol + 0, arow) = f2tf32(ar.x);
    RB_AS(0, acol + 1, arow) = f2tf32(ar.y);
    RB_AS(0, acol + 2, arow) = f2tf32(ar.z);
    RB_AS(0, acol + 3, arow) = f2tf32(ar.w);
#pragma unroll
    for (int nv = 0; nv < 2; nv++) {
        int col = bcol + nv * 64;
        RB_B0(0, brow, col + 0) = f2tf32(b0r[nv].x);
        RB_B0(0, brow, col + 1) = f2tf32(b0r[nv].y);
        RB_B0(0, brow, col + 2) = f2tf32(b0r[nv].z);
        RB_B0(0, brow, col + 3) = f2tf32(b0r[nv].w);
        RB_BS(0, brow, col + 0) = f2tf32(bsr[nv].x);
        RB_BS(0, brow, col + 1) = f2tf32(bsr[nv].y);
        RB_BS(0, brow, col + 2) = f2tf32(bsr[nv].z);
        RB_BS(0, brow, col + 3) = f2tf32(bsr[nv].w);
    }
    __syncthreads();

    for (int kt = 0; kt < 16; kt++) {
        int cur = kt & 1;
        if (kt + 1 < 16) {
            int k0 = (kt + 1) * 16;
            ar = loadA(k0);
#pragma unroll
            for (int nv = 0; nv < 2; nv++) {
                b0r[nv] = *(const float4*)&w0[(size_t)(k0 + brow) * H + bcol + nv * 64];
                bsr[nv] = *(const float4*)&ws[(size_t)(k0 + brow) * H + bcol + nv * 64];
            }
        }
#pragma unroll
        for (int ks = 0; ks < 2; ks++) {
            unsigned afr[2][4], afh[2][4], bf0[4][2], bfs[4][2];
#pragma unroll
            for (int mi = 0; mi < 2; mi++) {
                int m = wm * 32 + mi * 16 + lr;
                int k = ks * 8 + lc;
                afr[mi][0] = RB_AS(cur, k, m);
                afr[mi][1] = RB_AS(cur, k, m + 8);
                afr[mi][2] = RB_AS(cur, k + 4, m);
                afr[mi][3] = RB_AS(cur, k + 4, m + 8);
#pragma unroll
                for (int q = 0; q < 4; q++)
                    afh[mi][q] = __float_as_uint(fmaxf(__uint_as_float(afr[mi][q]), 0.f));
            }
#pragma unroll
            for (int ni = 0; ni < 4; ni++) {
                int n = wn * 32 + ni * 8 + lr;
                bf0[ni][0] = RB_B0(cur, ks * 8 + lc, n);
                bf0[ni][1] = RB_B0(cur, ks * 8 + 4 + lc, n);
                bfs[ni][0] = RB_BS(cur, ks * 8 + lc, n);
                bfs[ni][1] = RB_BS(cur, ks * 8 + 4 + lc, n);
            }
#pragma unroll
            for (int mi = 0; mi < 2; mi++)
#pragma unroll
                for (int ni = 0; ni < 4; ni++) {
                    asm volatile(
                        "mma.sync.aligned.m16n8k8.row.col.f32.tf32.tf32.f32 "
                        "{%0,%1,%2,%3}, {%4,%5,%6,%7}, {%8,%9}, {%0,%1,%2,%3};"
                        : "+f"(accH[mi][ni][0]), "+f"(accH[mi][ni][1]),
                          "+f"(accH[mi][ni][2]), "+f"(accH[mi][ni][3])
                        : "r"(afh[mi][0]), "r"(afh[mi][1]), "r"(afh[mi][2]), "r"(afh[mi][3]),
                          "r"(bf0[ni][0]), "r"(bf0[ni][1]));
                    asm volatile(
                        "mma.sync.aligned.m16n8k8.row.col.f32.tf32.tf32.f32 "
                        "{%0,%1,%2,%3}, {%4,%5,%6,%7}, {%8,%9}, {%0,%1,%2,%3};"
                        : "+f"(accS[mi][ni][0]), "+f"(accS[mi][ni][1]),
                          "+f"(accS[mi][ni][2]), "+f"(accS[mi][ni][3])
                        : "r"(afr[mi][0]), "r"(afr[mi][1]), "r"(afr[mi][2]), "r"(afr[mi][3]),
                          "r"(bfs[ni][0]), "r"(bfs[ni][1]));
                }
        }
        if (kt + 1 < 16) {
            int nxt = cur ^ 1;
            RB_AS(nxt, acol + 0, arow) = f2tf32(ar.x);
            RB_AS(nxt, acol + 1, arow) = f2tf32(ar.y);
            RB_AS(nxt, acol + 2, arow) = f2tf32(ar.z);
            RB_AS(nxt, acol + 3, arow) = f2tf32(ar.w);
#pragma unroll
            for (int nv = 0; nv < 2; nv++) {
                int col = bcol + nv * 64;
                RB_B0(nxt, brow, col + 0) = f2tf32(b0r[nv].x);
                RB_B0(nxt, brow, col + 1) = f2tf32(b0r[nv].y);
                RB_B0(nxt, brow, col + 2) = f2tf32(b0r[nv].z);
                RB_B0(nxt, brow, col + 3) = f2tf32(b0r[nv].w);
                RB_BS(nxt, brow, col + 0) = f2tf32(bsr[nv].x);
                RB_BS(nxt, brow, col + 1) = f2tf32(bsr[nv].y);
                RB_BS(nxt, brow, col + 2) = f2tf32(bsr[nv].z);
                RB_BS(nxt, brow, col + 3) = f2tf32(bsr[nv].w);
            }
        }
        __syncthreads();
    }

    // ---- store Hs = relu(accH + b0) (layout [n][m], tf32) ----
#pragma unroll
    for (int mi = 0; mi < 2; mi++)
#pragma unroll
        for (int ni = 0; ni < 4; ni++) {
            int n = wn * 32 + ni * 8 + lc * 2;
            float bv0 = b0[n], bv1 = b0[n + 1];
#pragma unroll
            for (int half = 0; half < 2; half++) {
                int m = wm * 32 + mi * 16 + lr + half * 8;
                RB_HS(n, m)     = f2tf32(fmaxf(accH[mi][ni][half * 2 + 0] + bv0, 0.f));
                RB_HS(n + 1, m) = f2tf32(fmaxf(accH[mi][ni][half * 2 + 1] + bv1, 0.f));
            }
        }
#pragma unroll
    for (int nv = 0; nv < 2; nv++)
        b0r[nv] = *(const float4*)&w1[(size_t)brow * H + bcol + nv * 64];
    __syncthreads();   // Hs visible; phase-1 B0s dead
#pragma unroll
    for (int nv = 0; nv < 2; nv++) {
        int col = bcol + nv * 64;
        RB_B0(0, brow, col + 0) = f2tf32(b0r[nv].x);
        RB_B0(0, brow, col + 1) = f2tf32(b0r[nv].y);
        RB_B0(0, brow, col + 2) = f2tf32(b0r[nv].z);
        RB_B0(0, brow, col + 3) = f2tf32(b0r[nv].w);
    }
    __syncthreads();

    // ---- phase 2: accS += Hs @ w1, K=128 ----
    for (int kt = 0; kt < 8; kt++) {
        int cur = kt & 1;
        if (kt + 1 < 8) {
            int k0 = (kt + 1) * 16;
#pragma unroll
            for (int nv = 0; nv < 2; nv++)
                b0r[nv] = *(const float4*)&w1[(size_t)(k0 + brow) * H + bcol + nv * 64];
        }
#pragma unroll
        for (int ks = 0; ks < 2; ks++) {
            unsigned af[2][4], bf[4][2];
            int kk = kt * 16 + ks * 8 + lc;
#pragma unroll
            for (int mi = 0; mi < 2; mi++) {
                int m = wm * 32 + mi * 16 + lr;
                af[mi][0] = RB_HS(kk, m);
                af[mi][1] = RB_HS(kk, m + 8);
                af[mi][2] = RB_HS(kk + 4, m);
                af[mi][3] = RB_HS(kk + 4, m + 8);
            }
#pragma unroll
            for (int ni = 0; ni < 4; ni++) {
                int n = wn * 32 + ni * 8 + lr;
                bf[ni][0] = RB_B0(cur, ks * 8 + lc, n);
                bf[ni][1] = RB_B0(cur, ks * 8 + 4 + lc, n);
            }
#pragma unroll
            for (int mi = 0; mi < 2; mi++)
#pragma unroll
                for (int ni = 0; ni < 4; ni++) {
                    asm volatile(
                        "mma.sync.aligned.m16n8k8.row.col.f32.tf32.tf32.f32 "
                        "{%0,%1,%2,%3}, {%4,%5,%6,%7}, {%8,%9}, {%0,%1,%2,%3};"
                        : "+f"(accS[mi][ni][0]), "+f"(accS[mi][ni][1]),
                          "+f"(accS[mi][ni][2]), "+f"(accS[mi][ni][3])
                        : "r"(af[mi][0]), "r"(af[mi][1]), "r"(af[mi][2]), "r"(af[mi][3]),
                          "r"(bf[ni][0]), "r"(bf[ni][1]));
                }
        }
        if (kt + 1 < 8) {
            int nxt = cur ^ 1;
#pragma unroll
            for (int nv = 0; nv < 2; nv++) {
                int col = bcol + nv * 64;
                RB_B0(nxt, brow, col + 0) = f2tf32(b0r[nv].x);
                RB_B0(nxt, brow, col + 1) = f2tf32(b0r[nv].y);
                RB_B0(nxt, brow, col + 2) = f2tf32(b0r[nv].z);
                RB_B0(nxt, brow, col + 3) = f2tf32(b0r[nv].w);
            }
        }
        __syncthreads();
    }

    // ---- epilogue: NET = fp16(accS + b1) ----
#pragma unroll
    for (int mi = 0; mi < 2; mi++)
#pragma unroll
        for (int ni = 0; ni < 4; ni++) {
            int n = wn * 32 + ni * 8 + lc * 2;
            float bv0 = b1[n], bv1 = b1[n + 1];
#pragma unroll
            for (int half = 0; half < 2; half++) {
                int m = bm + wm * 32 + mi * 16 + lr + half * 8;
                *(__half2*)&NET[(size_t)m * H + n] =
                    __floats2half2_rn(accS[mi][ni][half * 2 + 0] + bv0,
                                      accS[mi][ni][half * 2 + 1] + bv1);
            }
        }
}

// ---------------- TF32 GEMM for fc_c (A in fp16) ----------------
template <int BN, bool BIAS, int WARPS_M, int WARPS_N>
__global__ void __launch_bounds__(256)
k_mma(const __half* __restrict__ A, const float* __restrict__ W,
      const float* __restrict__ bias, float* __restrict__ C,
      int M, int K) {
    constexpr int BM = 128, BK = 16;
    constexpr int WM = BM / WARPS_M, WN = BN / WARPS_N;
    constexpr int TM = WM / 16, TN = WN / 8;
    constexpr int ASr = BM + 8, BSr = BN + 8;
    __shared__ unsigned As[2][BK][ASr];
    __shared__ unsigned Bs[2][BK][BSr];
    int tid = threadIdx.x;
    int bm = blockIdx.x * BM;
    int w = tid >> 5, lane = tid & 31;
    int wm = w % WARPS_M, wn = w / WARPS_M;
    int lr = lane >> 2, lc = lane & 3;

    float acc[TM][TN][4];
#pragma unroll
    for (int mi = 0; mi < TM; mi++)
#pragma unroll
        for (int ni = 0; ni < TN; ni++)
#pragma unroll
            for (int q = 0; q < 4; q++) acc[mi][ni][q] = 0.0f;

    int arow = tid >> 2;
    int acol = (tid & 3) * 4;
    int brow = tid >> 4;
    int bcol = (tid & 15) * 4;

    uint2 ah[2];
    float4 br;

    auto stA = [&](int buf, uint2 u, int rowidx) {
        float2 n0 = __half22float2(*(__half2*)&u.x);
        float2 n1 = __half22float2(*(__half2*)&u.y);
        As[buf][acol + 0][rowidx] = f2tf32(n0.x);
        As[buf][acol + 1][rowidx] = f2tf32(n0.y);
        As[buf][acol + 2][rowidx] = f2tf32(n1.x);
        As[buf][acol + 3][rowidx] = f2tf32(n1.y);
    };

    {
#pragma unroll
        for (int hh = 0; hh < 2; hh++)
            ah[hh] = *(const uint2*)&A[(size_t)(bm + arow + hh * 64) * K + acol];
        br = *(const float4*)&W[(size_t)brow * BN + bcol];
#pragma unroll
        for (int hh = 0; hh < 2; hh++) stA(0, ah[hh], arow + hh * 64);
        Bs[0][brow][bcol + 0] = f2tf32(br.x);
        Bs[0][brow][bcol + 1] = f2tf32(br.y);
        Bs[0][brow][bcol + 2] = f2tf32(br.z);
        Bs[0][brow][bcol + 3] = f2tf32(br.w);
    }
    __syncthreads();

    int KT = K / BK;
    for (int kt = 0; kt < KT; kt++) {
        int cur = kt & 1;
        if (kt + 1 < KT) {
            int k0 = (kt + 1) * BK;
#pragma unroll
            for (int hh = 0; hh < 2; hh++)
                ah[hh] = *(const uint2*)&A[(size_t)(bm + arow + hh * 64) * K + k0 + acol];
            br = *(const float4*)&W[(size_t)(k0 + brow) * BN + bcol];
        }
#pragma unroll
        for (int ks = 0; ks < 2; ks++) {
            unsigned af[TM][4], bf[TN][2];
#pragma unroll
            for (int mi = 0; mi < TM; mi++) {
                int m = wm * WM + mi * 16 + lr;
                int k = ks * 8 + lc;
                af[mi][0] = As[cur][k][m];
                af[mi][1] = As[cur][k][m + 8];
                af[mi][2] = As[cur][k + 4][m];
                af[mi][3] = As[cur][k + 4][m + 8];
            }
#pragma unroll
            for (int ni = 0; ni < TN; ni++) {
                int n = wn * WN + ni * 8 + lr;
                bf[ni][0] = Bs[cur][ks * 8 + lc][n];
                bf[ni][1] = Bs[cur][ks * 8 + 4 + lc][n];
            }
#pragma unroll
            for (int mi = 0; mi < TM; mi++)
#pragma unroll
                for (int ni = 0; ni < TN; ni++) {
                    asm volatile(
                        "mma.sync.aligned.m16n8k8.row.col.f32.tf32.tf32.f32 "
                        "{%0,%1,%2,%3}, {%4,%5,%6,%7}, {%8,%9}, {%0,%1,%2,%3};"
                        : "+f"(acc[mi][ni][0]), "+f"(acc[mi][ni][1]),
                          "+f"(acc[mi][ni][2]), "+f"(acc[mi][ni][3])
                        : "r"(af[mi][0]), "r"(af[mi][1]), "r"(af[mi][2]), "r"(af[mi][3]),
                          "r"(bf[ni][0]), "r"(bf[ni][1]));
                }
        }
        if (kt + 1 < KT) {
            int nxt = cur ^ 1;
#pragma unroll
            for (int hh = 0; hh < 2; hh++) stA(nxt, ah[hh], arow + hh * 64);
            Bs[nxt][brow][bcol + 0] = f2tf32(br.x);
            Bs[nxt][brow][bcol + 1] = f2tf32(br.y);
            Bs[nxt][brow][bcol + 2] = f2tf32(br.z);
            Bs[nxt][brow][bcol + 3] = f2tf32(br.w);
        }
        __syncthreads();
    }

#pragma unroll
    for (int mi = 0; mi < TM; mi++)
#pragma unroll
        for (int ni = 0; ni < TN; ni++) {
            int n = wn * WN + ni * 8 + lc * 2;
            float bv0 = 0.f, bv1 = 0.f;
            if (BIAS) { bv0 = bias[n]; bv1 = bias[n + 1]; }
#pragma unroll
            for (int half = 0; half < 2; half++) {
                int m = bm + wm * WM + mi * 16 + lr + half * 8;
                *(float2*)&C[(size_t)m * BN + n] =
                    make_float2(acc[mi][ni][half * 2 + 0] + bv0,
                                acc[mi][ni][half * 2 + 1] + bv1);
            }
        }
}

// ---------------- pooling (fp16 gather, hmax2) ----------------
__global__ void k_poolmax8() {
    int t = blockIdx.x * 256 + threadIdx.x;   // 3*NSEG*16
    int f8 = t & 15;                          // 8 channels per thread
    int bin = (t >> 4) & (NSEG - 1);
    int pl = t >> 20;
    int cnt = g_bcnt[pl][bin];
    if (cnt == 0) return;
    int off = g_boff[pl][bin] + g_bsum[pl][bin >> 11];
    __half2 mneg = __floats2half2_rn(-65504.f, -65504.f);
    __half2 m0 = mneg, m1 = mneg, m2 = mneg, m3 = mneg;
    for (int j = 0; j < cnt; j++) {
        int pt = g_pts[pl][off + j];
        uint4 v = *(const uint4*)&g_net[(size_t)pt * H + f8 * 8];
        m0 = __hmax2(m0, *(__half2*)&v.x);
        m1 = __hmax2(m1, *(__half2*)&v.y);
        m2 = __hmax2(m2, *(__half2*)&v.z);
        m3 = __hmax2(m3, *(__half2*)&v.w);
    }
    uint4 o;
    o.x = *(unsigned*)&m0; o.y = *(unsigned*)&m1;
    o.z = *(unsigned*)&m2; o.w = *(unsigned*)&m3;
    *(uint4*)&g_segmax[pl][(size_t)bin * H + f8 * 8] = o;
}

// ---------------- fused mean + transposed output ----------------
// out layout: [plane][b][ch][pix]
__global__ void __launch_bounds__(256)
k_meanout(float* __restrict__ out) {
    __shared__ float smean[32][72];       // 288 B rows: float4-aligned
    int pix0 = blockIdx.x * 32;
    int pb = blockIdx.y;                  // pl*4 + b
    int pl = pb >> 2, b = pb & 3;
    int t = threadIdx.x;

    int binl = t >> 3;                    // 32 bins, 8 threads each
    int c8 = (t & 7) * 8;                 // 8 channels per thread
    int bin = b * R2_ + pix0 + binl;
    int cnt = g_bcnt[pl][bin];
    float4 s0 = make_float4(0.f, 0.f, 0.f, 0.f);
    float4 s1 = make_float4(0.f, 0.f, 0.f, 0.f);
    if (cnt > 0) {
        int off = g_boff[pl][bin] + g_bsum[pl][bin >> 11];
        for (int j = 0; j < cnt; j++) {
            int pt = g_pts[pl][off + j];
            float4 v0 = *(const float4*)&g_c[(size_t)pt * CDIM + c8];
            float4 v1 = *(const float4*)&g_c[(size_t)pt * CDIM + c8 + 4];
            s0.x += v0.x; s0.y += v0.y; s0.z += v0.z; s0.w += v0.w;
            s1.x += v1.x; s1.y += v1.y; s1.z += v1.z; s1.w += v1.w;
        }
        float inv = 1.0f / (float)cnt;
        s0.x *= inv; s0.y *= inv; s0.z *= inv; s0.w *= inv;
        s1.x *= inv; s1.y *= inv; s1.z *= inv; s1.w *= inv;
    }
    *(float4*)&smean[binl][c8] = s0;
    *(float4*)&smean[binl][c8 + 4] = s1;
    __syncthreads();

    int tx = t & 31;          // pix
    int ty = t >> 5;          // 8 ch-groups
#pragma unroll
    for (int k = 0; k < 8; k++) {
        int ch = ty * 8 + k;
        out[((size_t)pb * CDIM + ch) * R2_ + pix0 + tx] = smean[tx][ch];
    }
}

// ---------------- launcher ----------------
extern "C" void kernel_launch(void* const* d_in, const int* in_sizes, int n_in,
                              void* d_out, int out_size) {
    const float* p   = (const float*)d_in[0];
    const float* fw  = (const float*)d_in[1];
    const float* fb  = (const float*)d_in[2];
    const float* w0  = (const float*)d_in[3];
    const float* b0  = (const float*)d_in[4];
    const float* w1  = (const float*)d_in[5];
    const float* b1  = (const float*)d_in[6];
    const float* ws  = (const float*)d_in[7];
    const float* fcw = (const float*)d_in[8];
    const float* fcb = (const float*)d_in[9];
    float* out = (float*)d_out;

    __half* gn;
    float* gc;
    cudaGetSymbolAddress((void**)&gn, g_net);
    cudaGetSymbolAddress((void**)&gc, g_c);

    static bool attr_done = false;
    if (!attr_done) {
        cudaFuncSetAttribute(k_resblock<0>,
                             cudaFuncAttributeMaxDynamicSharedMemorySize, RB_SMEM_BYTES);
        cudaFuncSetAttribute(k_resblock<1>,
                             cudaFuncAttributeMaxDynamicSharedMemorySize, RB_SMEM_BYTES);
        attr_done = true;
    }

    // CSR build, with rb<0> interleaved so the profiler's 4th-launch window
    // lands on the resblock.
    k_zerobcnt<<<(3 * NSEG) / 256, 256>>>();
    k_idxcount<<<BT / 256, 256>>>(p);
    k_scanA<<<dim3(32, 3), 1024>>>();
    k_resblock<0><<<BT / 64, 256, RB_SMEM_BYTES>>>(
        p, fw, fb, w0, b0, w1, b1, ws, gn);                      // 4th launch
    k_scanB<<<1, 96>>>();
    k_scatter<<<BT / 256, 256>>>();

    for (int i = 1; i < NB; i++) {
        k_poolmax8<<<(3 * NSEG * 16) / 256, 256>>>();
        k_resblock<1><<<BT / 64, 256, RB_SMEM_BYTES>>>(
            nullptr, nullptr, nullptr,
            w0 + (size_t)i * H2 * H, b0 + (size_t)i * H,
            w1 + (size_t)i * H * H, b1 + (size_t)i * H,
            ws + (size_t)i * H2 * H, gn);
    }

    // c = net @ fc_c_w + fc_c_b
    k_mma<64, true, 4, 2><<<BT / 128, 256>>>(gn, fcw, fcb, gc, BT, H);

    k_meanout<<<dim3(R2_ / 32, 3 * B_), 256>>>(out);
}